// round 1
// baseline (speedup 1.0000x reference)
#include <cuda_runtime.h>

#define Bb 4
#define Tt 1024
#define Vv 32000
#define Ee 1024
#define Hh 16
#define HSs 64
#define Mm 4096  // B*T

// ---------------- scratch (static device globals; no runtime allocation) ----
__device__ float g_x[(size_t)Mm * Ee];          // embedded input  (B*T, E)
__device__ float g_k[(size_t)Bb * Hh * Tt * HSs];
__device__ float g_q[(size_t)Bb * Hh * Tt * HSs];
__device__ float g_v[(size_t)Bb * Hh * Tt * HSs];
__device__ float g_z[(size_t)Mm * Ee];          // attention out, heads concat
__device__ float g_f[(size_t)Mm * Ee];          // after FF+ReLU

// ---------------- embed: x = tok_emb[inputs] + pos_emb[:T] ------------------
__global__ void embed_kernel(const int* __restrict__ inp,
                             const float* __restrict__ tok,
                             const float* __restrict__ pos) {
    int row = blockIdx.x;            // b*T + t
    int t   = row & (Tt - 1);
    int id  = inp[row];
    const float4* te = (const float4*)(tok + (size_t)id * Ee);
    const float4* pe = (const float4*)(pos + (size_t)t * Ee);
    float4* xo = (float4*)(g_x + (size_t)row * Ee);
    int i = threadIdx.x;             // 256 threads == E/4 float4 per row
    float4 a = te[i], b = pe[i];
    xo[i] = make_float4(a.x + b.x, a.y + b.y, a.z + b.z, a.w + b.w);
}

// ---------------- QKV: per-head GEMM  (M=4096, N=64, K=1024) ----------------
// out[((b*H+h)*T + t)*HS + d] = sum_e x[b,t,e] * W[h,e,d]
__global__ void qkv_kernel(const float* __restrict__ Wk,
                           const float* __restrict__ Wq,
                           const float* __restrict__ Wv) {
    int which = blockIdx.z;
    const float* W = (which == 0) ? Wk : (which == 1) ? Wq : Wv;
    float* out = (which == 0) ? g_k : (which == 1) ? g_q : g_v;
    int h = blockIdx.y;
    const float* Wh = W + (size_t)h * Ee * HSs;   // (E, 64) row-major
    int m0 = blockIdx.x * 128;

    __shared__ __align__(16) float As[16][128];
    __shared__ __align__(16) float Bs[16][64];

    float acc[8][4];
#pragma unroll
    for (int i = 0; i < 8; i++)
#pragma unroll
        for (int j = 0; j < 4; j++) acc[i][j] = 0.f;

    int tid = threadIdx.x;
    int ty = tid >> 4, tx = tid & 15;

    for (int k0 = 0; k0 < Ee; k0 += 16) {
#pragma unroll
        for (int l = 0; l < 2; l++) {
            int idx = tid * 2 + l, ar = idx >> 2, ac4 = idx & 3;
            float4 a4 = *(const float4*)(g_x + (size_t)(m0 + ar) * Ee + k0 + ac4 * 4);
            As[ac4 * 4 + 0][ar] = a4.x;
            As[ac4 * 4 + 1][ar] = a4.y;
            As[ac4 * 4 + 2][ar] = a4.z;
            As[ac4 * 4 + 3][ar] = a4.w;
        }
        {
            int br = tid >> 4, bc4 = tid & 15;
            *(float4*)&Bs[br][bc4 * 4] =
                *(const float4*)(Wh + (size_t)(k0 + br) * HSs + bc4 * 4);
        }
        __syncthreads();
#pragma unroll
        for (int kk = 0; kk < 16; kk++) {
            float a[8], bb[4];
            *(float4*)(a)     = *(float4*)&As[kk][ty * 8];
            *(float4*)(a + 4) = *(float4*)&As[kk][ty * 8 + 4];
            *(float4*)(bb)    = *(float4*)&Bs[kk][tx * 4];
#pragma unroll
            for (int i = 0; i < 8; i++)
#pragma unroll
                for (int j = 0; j < 4; j++) acc[i][j] += a[i] * bb[j];
        }
        __syncthreads();
    }
#pragma unroll
    for (int i = 0; i < 8; i++) {
        int m = m0 + ty * 8 + i;
        int b = m >> 10, t = m & 1023;
        float* o = out + ((size_t)(b * Hh + h) * Tt + t) * HSs + tx * 4;
        *(float4*)o = make_float4(acc[i][0], acc[i][1], acc[i][2], acc[i][3]);
    }
}

// ---------------- flash attention -------------------------------------------
// Reference computes wei[t,s] = k_t . q_s (roles: Q:=k, K:=q, V:=v),
// causal s<=t, softmax over s, out[t] = sum_s wei * v_s.
// Grid: (B*H, T/64). 256 threads. 64x64 tiles, online softmax.
__global__ void attn_kernel() {
    extern __shared__ __align__(16) float sm[];
    float* Qs  = sm;             // [64][64]
    float* KsT = Qs + 64 * 64;   // [64][65]  (KsT[d][s], padded stride 65)
    float* Vs  = KsT + 64 * 65;  // [64][64]  (Vs[s][d])
    float* Ps  = Vs + 64 * 64;   // [64][64]

    int bh = blockIdx.x;         // b*H + h
    int rt = blockIdx.y;         // row tile (t-block)
    const float* Qb = g_k + (size_t)bh * Tt * HSs;
    const float* Kb = g_q + (size_t)bh * Tt * HSs;
    const float* Vb = g_v + (size_t)bh * Tt * HSs;

    int tid = threadIdx.x;
    int ty = tid >> 4, tx = tid & 15;

    for (int i = tid; i < 1024; i += 256) {
        int r = i >> 4, c4 = i & 15;
        *(float4*)&Qs[r * 64 + c4 * 4] =
            *(const float4*)(Qb + (size_t)(rt * 64 + r) * 64 + c4 * 4);
    }

    float mr[4], lr[4], O[4][4];
#pragma unroll
    for (int i = 0; i < 4; i++) {
        mr[i] = -1e30f; lr[i] = 0.f;
#pragma unroll
        for (int j = 0; j < 4; j++) O[i][j] = 0.f;
    }

    const unsigned FULL = 0xffffffffu;
    const float scl = 0.125f;  // HS^-0.5

    for (int st = 0; st <= rt; st++) {
        for (int i = tid; i < 1024; i += 256) {
            int r = i >> 4, c4 = i & 15;
            float4 kv = *(const float4*)(Kb + (size_t)(st * 64 + r) * 64 + c4 * 4);
            KsT[(c4 * 4 + 0) * 65 + r] = kv.x;
            KsT[(c4 * 4 + 1) * 65 + r] = kv.y;
            KsT[(c4 * 4 + 2) * 65 + r] = kv.z;
            KsT[(c4 * 4 + 3) * 65 + r] = kv.w;
            *(float4*)&Vs[r * 64 + c4 * 4] =
                *(const float4*)(Vb + (size_t)(st * 64 + r) * 64 + c4 * 4);
        }
        __syncthreads();

        float S[4][4];
#pragma unroll
        for (int i = 0; i < 4; i++)
#pragma unroll
            for (int j = 0; j < 4; j++) S[i][j] = 0.f;

#pragma unroll 16
        for (int kk = 0; kk < 64; kk++) {
            float a[4], bb[4];
#pragma unroll
            for (int i = 0; i < 4; i++) a[i] = Qs[(ty * 4 + i) * 64 + kk];
#pragma unroll
            for (int j = 0; j < 4; j++) bb[j] = KsT[kk * 65 + tx * 4 + j];
#pragma unroll
            for (int i = 0; i < 4; i++)
#pragma unroll
                for (int j = 0; j < 4; j++) S[i][j] += a[i] * bb[j];
        }

#pragma unroll
        for (int i = 0; i < 4; i++)
#pragma unroll
            for (int j = 0; j < 4; j++) {
                float s = S[i][j] * scl;
                if (st == rt && (tx * 4 + j) > (ty * 4 + i)) s = -1e30f;
                S[i][j] = s;
            }

#pragma unroll
        for (int i = 0; i < 4; i++) {
            float rm = fmaxf(fmaxf(S[i][0], S[i][1]), fmaxf(S[i][2], S[i][3]));
#pragma unroll
            for (int o = 1; o < 16; o <<= 1)
                rm = fmaxf(rm, __shfl_xor_sync(FULL, rm, o));
            float nm = fmaxf(mr[i], rm);
            float alpha = __expf(mr[i] - nm);
            float rs = 0.f;
#pragma unroll
            for (int j = 0; j < 4; j++) {
                S[i][j] = __expf(S[i][j] - nm);
                rs += S[i][j];
            }
#pragma unroll
            for (int o = 1; o < 16; o <<= 1)
                rs += __shfl_xor_sync(FULL, rs, o);
            lr[i] = lr[i] * alpha + rs;
            mr[i] = nm;
#pragma unroll
            for (int j = 0; j < 4; j++) O[i][j] *= alpha;
        }

#pragma unroll
        for (int i = 0; i < 4; i++)
            *(float4*)&Ps[(ty * 4 + i) * 64 + tx * 4] =
                make_float4(S[i][0], S[i][1], S[i][2], S[i][3]);
        __syncthreads();

#pragma unroll 8
        for (int c = 0; c < 64; c++) {
            float4 vv = *(float4*)&Vs[c * 64 + tx * 4];
#pragma unroll
            for (int i = 0; i < 4; i++) {
                float p = Ps[(ty * 4 + i) * 64 + c];
                O[i][0] += p * vv.x;
                O[i][1] += p * vv.y;
                O[i][2] += p * vv.z;
                O[i][3] += p * vv.w;
            }
        }
        __syncthreads();
    }

    int b = bh >> 4, h = bh & 15;
#pragma unroll
    for (int i = 0; i < 4; i++) {
        int t = rt * 64 + ty * 4 + i;
        float inv = 1.f / lr[i];
        *(float4*)&g_z[((size_t)(b * Tt + t)) * Ee + h * HSs + tx * 4] =
            make_float4(O[i][0] * inv, O[i][1] * inv, O[i][2] * inv, O[i][3] * inv);
    }
}

// ---------------- generic 128x128x16 SGEMM, K=1024, bias (+optional ReLU) ---
template <bool RELU>
__global__ void sgemm_kernel(const float* __restrict__ A,
                             const float* __restrict__ Bm,
                             const float* __restrict__ bias,
                             float* __restrict__ C, int N) {
    int n0 = blockIdx.x * 128, m0 = blockIdx.y * 128;
    __shared__ __align__(16) float As[16][128];
    __shared__ __align__(16) float Bs[16][128];

    float acc[8][8];
#pragma unroll
    for (int i = 0; i < 8; i++)
#pragma unroll
        for (int j = 0; j < 8; j++) acc[i][j] = 0.f;

    int tid = threadIdx.x;
    int ty = tid >> 4, tx = tid & 15;

    for (int k0 = 0; k0 < Ee; k0 += 16) {
#pragma unroll
        for (int l = 0; l < 2; l++) {
            int idx = tid * 2 + l;
            int ar = idx >> 2, ac4 = idx & 3;
            float4 a4 = *(const float4*)(A + (size_t)(m0 + ar) * Ee + k0 + ac4 * 4);
            As[ac4 * 4 + 0][ar] = a4.x;
            As[ac4 * 4 + 1][ar] = a4.y;
            As[ac4 * 4 + 2][ar] = a4.z;
            As[ac4 * 4 + 3][ar] = a4.w;
            int br = idx >> 5, bc4 = idx & 31;
            *(float4*)&Bs[br][bc4 * 4] =
                *(const float4*)(Bm + (size_t)(k0 + br) * N + n0 + bc4 * 4);
        }
        __syncthreads();
#pragma unroll
        for (int kk = 0; kk < 16; kk++) {
            float a[8], bb[8];
            *(float4*)(a)      = *(float4*)&As[kk][ty * 8];
            *(float4*)(a + 4)  = *(float4*)&As[kk][ty * 8 + 4];
            *(float4*)(bb)     = *(float4*)&Bs[kk][tx * 8];
            *(float4*)(bb + 4) = *(float4*)&Bs[kk][tx * 8 + 4];
#pragma unroll
            for (int i = 0; i < 8; i++)
#pragma unroll
                for (int j = 0; j < 8; j++) acc[i][j] += a[i] * bb[j];
        }
        __syncthreads();
    }

#pragma unroll
    for (int i = 0; i < 8; i++) {
        int m = m0 + ty * 8 + i;
#pragma unroll
        for (int j = 0; j < 8; j++) {
            int n = n0 + tx * 8 + j;
            float v = acc[i][j] + bias[n];
            if (RELU) v = fmaxf(v, 0.f);
            acc[i][j] = v;
        }
        float* cp = C + (size_t)m * N + n0 + tx * 8;
        *(float4*)(cp)     = make_float4(acc[i][0], acc[i][1], acc[i][2], acc[i][3]);
        *(float4*)(cp + 4) = make_float4(acc[i][4], acc[i][5], acc[i][6], acc[i][7]);
    }
}

// ---------------- launch -----------------------------------------------------
extern "C" void kernel_launch(void* const* d_in, const int* in_sizes, int n_in,
                              void* d_out, int out_size) {
    (void)in_sizes; (void)n_in; (void)out_size;
    const int*   inp = (const int*)d_in[0];
    const float* tok = (const float*)d_in[1];
    const float* pos = (const float*)d_in[2];
    const float* Wk  = (const float*)d_in[3];
    const float* Wq  = (const float*)d_in[4];
    const float* Wv  = (const float*)d_in[5];
    const float* ffW = (const float*)d_in[6];
    const float* ffb = (const float*)d_in[7];
    const float* oW  = (const float*)d_in[8];
    const float* ob  = (const float*)d_in[9];
    float* out = (float*)d_out;

    void *pz = nullptr, *pf = nullptr;
    cudaGetSymbolAddress(&pz, g_z);
    cudaGetSymbolAddress(&pf, g_f);

    embed_kernel<<<Mm, 256>>>(inp, tok, pos);
    qkv_kernel<<<dim3(Mm / 128, Hh, 3), 256>>>(Wk, Wq, Wv);

    size_t smem = (size_t)(64 * 64 + 64 * 65 + 64 * 64 + 64 * 64) * sizeof(float);
    cudaFuncSetAttribute(attn_kernel, cudaFuncAttributeMaxDynamicSharedMemorySize,
                         (int)smem);
    attn_kernel<<<dim3(Bb * Hh, Tt / 64), 256, smem>>>();

    sgemm_kernel<true><<<dim3(Ee / 128, Mm / 128), 256>>>(
        (const float*)pz, ffW, ffb, (float*)pf, Ee);
    sgemm_kernel<false><<<dim3(Vv / 128, Mm / 128), 256>>>(
        (const float*)pf, oW, ob, out, Vv);
}

// round 3
// speedup vs baseline: 2.0706x; 2.0706x over previous
#include <cuda_runtime.h>
#include <cuda_bf16.h>
#include <cstdint>

#define Bb 4
#define Tt 1024
#define Vv 32000
#define Ee 1024
#define Hh 16
#define HSs 64
#define Mm 4096  // B*T

// ---------------- scratch (static device globals; no runtime allocation) ----
__device__ float g_x[(size_t)Mm * Ee];
__device__ float g_k[(size_t)Bb * Hh * Tt * HSs];
__device__ float g_q[(size_t)Bb * Hh * Tt * HSs];
__device__ float g_v[(size_t)Bb * Hh * Tt * HSs];
__device__ float g_z[(size_t)Mm * Ee];
__device__ float g_f[(size_t)Mm * Ee];
__device__ __nv_bfloat16 g_Ahi[(size_t)Mm * Ee];
__device__ __nv_bfloat16 g_Alo[(size_t)Mm * Ee];
__device__ __nv_bfloat16 g_Bhi[(size_t)Vv * Ee];   // [V][K] (transposed out_W)
__device__ __nv_bfloat16 g_Blo[(size_t)Vv * Ee];

// ===================== arch-neutral PTX helpers (sm_80+) ====================
__device__ __forceinline__ uint32_t smem_u32(const void* p) {
    uint32_t a;
    asm("{ .reg .u64 t; cvta.to.shared.u64 t, %1; cvt.u32.u64 %0, t; }"
        : "=r"(a) : "l"(p));
    return a;
}
__device__ __forceinline__ void ldsm4(uint32_t* r, uint32_t addr) {
    asm volatile("ldmatrix.sync.aligned.m8n8.x4.shared.b16 {%0,%1,%2,%3}, [%4];"
                 : "=r"(r[0]), "=r"(r[1]), "=r"(r[2]), "=r"(r[3]) : "r"(addr));
}
__device__ __forceinline__ void ldsm2(uint32_t* r, uint32_t addr) {
    asm volatile("ldmatrix.sync.aligned.m8n8.x2.shared.b16 {%0,%1}, [%2];"
                 : "=r"(r[0]), "=r"(r[1]) : "r"(addr));
}
__device__ __forceinline__ void mma_bf16(float* c, const uint32_t* a,
                                         const uint32_t* b) {
    asm volatile(
        "mma.sync.aligned.m16n8k16.row.col.f32.bf16.bf16.f32 "
        "{%0,%1,%2,%3}, {%4,%5,%6,%7}, {%8,%9}, {%0,%1,%2,%3};"
        : "+f"(c[0]), "+f"(c[1]), "+f"(c[2]), "+f"(c[3])
        : "r"(a[0]), "r"(a[1]), "r"(a[2]), "r"(a[3]), "r"(b[0]), "r"(b[1]));
}
#define CP16(dst, src) \
    asm volatile("cp.async.cg.shared.global [%0], [%1], 16;" \
                 :: "r"(dst), "l"(src))
#define CP_COMMIT() asm volatile("cp.async.commit_group;" ::: "memory")
#define CP_WAIT(n)  asm volatile("cp.async.wait_group %0;" :: "n"(n) : "memory")

// ---------------- embed ------------------------------------------------------
__global__ void embed_kernel(const int* __restrict__ inp,
                             const float* __restrict__ tok,
                             const float* __restrict__ pos) {
    int row = blockIdx.x;
    int t   = row & (Tt - 1);
    int id  = inp[row];
    const float4* te = (const float4*)(tok + (size_t)id * Ee);
    const float4* pe = (const float4*)(pos + (size_t)t * Ee);
    float4* xo = (float4*)(g_x + (size_t)row * Ee);
    int i = threadIdx.x;
    float4 a = te[i], b = pe[i];
    xo[i] = make_float4(a.x + b.x, a.y + b.y, a.z + b.z, a.w + b.w);
}

// ---------------- QKV --------------------------------------------------------
__global__ void qkv_kernel(const float* __restrict__ Wk,
                           const float* __restrict__ Wq,
                           const float* __restrict__ Wv) {
    int which = blockIdx.z;
    const float* W = (which == 0) ? Wk : (which == 1) ? Wq : Wv;
    float* out = (which == 0) ? g_k : (which == 1) ? g_q : g_v;
    int h = blockIdx.y;
    const float* Wh = W + (size_t)h * Ee * HSs;
    int m0 = blockIdx.x * 128;

    __shared__ __align__(16) float As[16][128];
    __shared__ __align__(16) float Bs[16][64];

    float acc[8][4];
#pragma unroll
    for (int i = 0; i < 8; i++)
#pragma unroll
        for (int j = 0; j < 4; j++) acc[i][j] = 0.f;

    int tid = threadIdx.x;
    int ty = tid >> 4, tx = tid & 15;

    for (int k0 = 0; k0 < Ee; k0 += 16) {
#pragma unroll
        for (int l = 0; l < 2; l++) {
            int idx = tid * 2 + l, ar = idx >> 2, ac4 = idx & 3;
            float4 a4 = *(const float4*)(g_x + (size_t)(m0 + ar) * Ee + k0 + ac4 * 4);
            As[ac4 * 4 + 0][ar] = a4.x;
            As[ac4 * 4 + 1][ar] = a4.y;
            As[ac4 * 4 + 2][ar] = a4.z;
            As[ac4 * 4 + 3][ar] = a4.w;
        }
        {
            int br = tid >> 4, bc4 = tid & 15;
            *(float4*)&Bs[br][bc4 * 4] =
                *(const float4*)(Wh + (size_t)(k0 + br) * HSs + bc4 * 4);
        }
        __syncthreads();
#pragma unroll
        for (int kk = 0; kk < 16; kk++) {
            float a[8], bb[4];
            *(float4*)(a)     = *(float4*)&As[kk][ty * 8];
            *(float4*)(a + 4) = *(float4*)&As[kk][ty * 8 + 4];
            *(float4*)(bb)    = *(float4*)&Bs[kk][tx * 4];
#pragma unroll
            for (int i = 0; i < 8; i++)
#pragma unroll
                for (int j = 0; j < 4; j++) acc[i][j] += a[i] * bb[j];
        }
        __syncthreads();
    }
#pragma unroll
    for (int i = 0; i < 8; i++) {
        int m = m0 + ty * 8 + i;
        int b = m >> 10, t = m & 1023;
        float* o = out + ((size_t)(b * Hh + h) * Tt + t) * HSs + tx * 4;
        *(float4*)o = make_float4(acc[i][0], acc[i][1], acc[i][2], acc[i][3]);
    }
}

// ---------------- flash attention -------------------------------------------
__global__ void attn_kernel() {
    extern __shared__ __align__(16) float sm[];
    float* Qs  = sm;
    float* KsT = Qs + 64 * 64;
    float* Vs  = KsT + 64 * 65;
    float* Ps  = Vs + 64 * 64;

    int bh = blockIdx.x;
    int rt = blockIdx.y;
    const float* Qb = g_k + (size_t)bh * Tt * HSs;
    const float* Kb = g_q + (size_t)bh * Tt * HSs;
    const float* Vb = g_v + (size_t)bh * Tt * HSs;

    int tid = threadIdx.x;
    int ty = tid >> 4, tx = tid & 15;

    for (int i = tid; i < 1024; i += 256) {
        int r = i >> 4, c4 = i & 15;
        *(float4*)&Qs[r * 64 + c4 * 4] =
            *(const float4*)(Qb + (size_t)(rt * 64 + r) * 64 + c4 * 4);
    }

    float mr[4], lr[4], O[4][4];
#pragma unroll
    for (int i = 0; i < 4; i++) {
        mr[i] = -1e30f; lr[i] = 0.f;
#pragma unroll
        for (int j = 0; j < 4; j++) O[i][j] = 0.f;
    }

    const unsigned FULL = 0xffffffffu;
    const float scl = 0.125f;

    for (int st = 0; st <= rt; st++) {
        for (int i = tid; i < 1024; i += 256) {
            int r = i >> 4, c4 = i & 15;
            float4 kv = *(const float4*)(Kb + (size_t)(st * 64 + r) * 64 + c4 * 4);
            KsT[(c4 * 4 + 0) * 65 + r] = kv.x;
            KsT[(c4 * 4 + 1) * 65 + r] = kv.y;
            KsT[(c4 * 4 + 2) * 65 + r] = kv.z;
            KsT[(c4 * 4 + 3) * 65 + r] = kv.w;
            *(float4*)&Vs[r * 64 + c4 * 4] =
                *(const float4*)(Vb + (size_t)(st * 64 + r) * 64 + c4 * 4);
        }
        __syncthreads();

        float S[4][4];
#pragma unroll
        for (int i = 0; i < 4; i++)
#pragma unroll
            for (int j = 0; j < 4; j++) S[i][j] = 0.f;

#pragma unroll 16
        for (int kk = 0; kk < 64; kk++) {
            float a[4], bb[4];
#pragma unroll
            for (int i = 0; i < 4; i++) a[i] = Qs[(ty * 4 + i) * 64 + kk];
#pragma unroll
            for (int j = 0; j < 4; j++) bb[j] = KsT[kk * 65 + tx * 4 + j];
#pragma unroll
            for (int i = 0; i < 4; i++)
#pragma unroll
                for (int j = 0; j < 4; j++) S[i][j] += a[i] * bb[j];
        }

#pragma unroll
        for (int i = 0; i < 4; i++)
#pragma unroll
            for (int j = 0; j < 4; j++) {
                float s = S[i][j] * scl;
                if (st == rt && (tx * 4 + j) > (ty * 4 + i)) s = -1e30f;
                S[i][j] = s;
            }

#pragma unroll
        for (int i = 0; i < 4; i++) {
            float rm = fmaxf(fmaxf(S[i][0], S[i][1]), fmaxf(S[i][2], S[i][3]));
#pragma unroll
            for (int o = 1; o < 16; o <<= 1)
                rm = fmaxf(rm, __shfl_xor_sync(FULL, rm, o));
            float nm = fmaxf(mr[i], rm);
            float alpha = __expf(mr[i] - nm);
            float rs = 0.f;
#pragma unroll
            for (int j = 0; j < 4; j++) {
                S[i][j] = __expf(S[i][j] - nm);
                rs += S[i][j];
            }
#pragma unroll
            for (int o = 1; o < 16; o <<= 1)
                rs += __shfl_xor_sync(FULL, rs, o);
            lr[i] = lr[i] * alpha + rs;
            mr[i] = nm;
#pragma unroll
            for (int j = 0; j < 4; j++) O[i][j] *= alpha;
        }

#pragma unroll
        for (int i = 0; i < 4; i++)
            *(float4*)&Ps[(ty * 4 + i) * 64 + tx * 4] =
                make_float4(S[i][0], S[i][1], S[i][2], S[i][3]);
        __syncthreads();

#pragma unroll 8
        for (int c = 0; c < 64; c++) {
            float4 vv = *(float4*)&Vs[c * 64 + tx * 4];
#pragma unroll
            for (int i = 0; i < 4; i++) {
                float p = Ps[(ty * 4 + i) * 64 + c];
                O[i][0] += p * vv.x;
                O[i][1] += p * vv.y;
                O[i][2] += p * vv.z;
                O[i][3] += p * vv.w;
            }
        }
        __syncthreads();
    }

    int b = bh >> 4, h = bh & 15;
#pragma unroll
    for (int i = 0; i < 4; i++) {
        int t = rt * 64 + ty * 4 + i;
        float inv = 1.f / lr[i];
        *(float4*)&g_z[((size_t)(b * Tt + t)) * Ee + h * HSs + tx * 4] =
            make_float4(O[i][0] * inv, O[i][1] * inv, O[i][2] * inv, O[i][3] * inv);
    }
}

// ---------------- FF SGEMM (fp32) -------------------------------------------
template <bool RELU>
__global__ void sgemm_kernel(const float* __restrict__ A,
                             const float* __restrict__ Bm,
                             const float* __restrict__ bias,
                             float* __restrict__ C, int N) {
    int n0 = blockIdx.x * 128, m0 = blockIdx.y * 128;
    __shared__ __align__(16) float As[16][128];
    __shared__ __align__(16) float Bs[16][128];

    float acc[8][8];
#pragma unroll
    for (int i = 0; i < 8; i++)
#pragma unroll
        for (int j = 0; j < 8; j++) acc[i][j] = 0.f;

    int tid = threadIdx.x;
    int ty = tid >> 4, tx = tid & 15;

    for (int k0 = 0; k0 < Ee; k0 += 16) {
#pragma unroll
        for (int l = 0; l < 2; l++) {
            int idx = tid * 2 + l;
            int ar = idx >> 2, ac4 = idx & 3;
            float4 a4 = *(const float4*)(A + (size_t)(m0 + ar) * Ee + k0 + ac4 * 4);
            As[ac4 * 4 + 0][ar] = a4.x;
            As[ac4 * 4 + 1][ar] = a4.y;
            As[ac4 * 4 + 2][ar] = a4.z;
            As[ac4 * 4 + 3][ar] = a4.w;
            int br = idx >> 5, bc4 = idx & 31;
            *(float4*)&Bs[br][bc4 * 4] =
                *(const float4*)(Bm + (size_t)(k0 + br) * N + n0 + bc4 * 4);
        }
        __syncthreads();
#pragma unroll
        for (int kk = 0; kk < 16; kk++) {
            float a[8], bb[8];
            *(float4*)(a)      = *(float4*)&As[kk][ty * 8];
            *(float4*)(a + 4)  = *(float4*)&As[kk][ty * 8 + 4];
            *(float4*)(bb)     = *(float4*)&Bs[kk][tx * 8];
            *(float4*)(bb + 4) = *(float4*)&Bs[kk][tx * 8 + 4];
#pragma unroll
            for (int i = 0; i < 8; i++)
#pragma unroll
                for (int j = 0; j < 8; j++) acc[i][j] += a[i] * bb[j];
        }
        __syncthreads();
    }

#pragma unroll
    for (int i = 0; i < 8; i++) {
        int m = m0 + ty * 8 + i;
#pragma unroll
        for (int j = 0; j < 8; j++) {
            int n = n0 + tx * 8 + j;
            float v = acc[i][j] + bias[n];
            if (RELU) v = fmaxf(v, 0.f);
            acc[i][j] = v;
        }
        float* cp = C + (size_t)m * N + n0 + tx * 8;
        *(float4*)(cp)     = make_float4(acc[i][0], acc[i][1], acc[i][2], acc[i][3]);
        *(float4*)(cp + 4) = make_float4(acc[i][4], acc[i][5], acc[i][6], acc[i][7]);
    }
}

// ---------------- bf16 hi/lo split ------------------------------------------
__global__ void cvt_split_kernel(const float* __restrict__ src,
                                 __nv_bfloat16* __restrict__ hi,
                                 __nv_bfloat16* __restrict__ lo) {
    int i = blockIdx.x * 256 + threadIdx.x;
    float4 v = ((const float4*)src)[i];
    __align__(8) __nv_bfloat16 h[4], l[4];
    float x[4] = {v.x, v.y, v.z, v.w};
#pragma unroll
    for (int j = 0; j < 4; j++) {
        h[j] = __float2bfloat16(x[j]);
        l[j] = __float2bfloat16(x[j] - __bfloat162float(h[j]));
    }
    *(uint2*)(hi + (size_t)i * 4) = *(uint2*)h;
    *(uint2*)(lo + (size_t)i * 4) = *(uint2*)l;
}

// ---------------- out_W [K][V] -> [V][K] bf16 hi/lo --------------------------
__global__ void cvt_transpose_kernel(const float* __restrict__ W,
                                     __nv_bfloat16* __restrict__ hi,
                                     __nv_bfloat16* __restrict__ lo) {
    __shared__ float tile[64][65];
    int nb = blockIdx.x * 64;
    int kb = blockIdx.y * 64;
    int tid = threadIdx.x;

    for (int i = tid; i < 1024; i += 256) {
        int r = i >> 4, c4 = i & 15;
        float4 v = *(const float4*)(W + (size_t)(kb + r) * Vv + nb + c4 * 4);
        tile[c4 * 4 + 0][r] = v.x;
        tile[c4 * 4 + 1][r] = v.y;
        tile[c4 * 4 + 2][r] = v.z;
        tile[c4 * 4 + 3][r] = v.w;
    }
    __syncthreads();

    for (int i = tid; i < 512; i += 256) {
        int nr = i >> 3, c = i & 7;
        __align__(16) __nv_bfloat16 hb[8], lb[8];
#pragma unroll
        for (int j = 0; j < 8; j++) {
            float x = tile[nr][c * 8 + j];
            __nv_bfloat16 h = __float2bfloat16(x);
            hb[j] = h;
            lb[j] = __float2bfloat16(x - __bfloat162float(h));
        }
        size_t dst = (size_t)(nb + nr) * Ee + kb + c * 8;
        *(uint4*)(hi + dst) = *(uint4*)hb;
        *(uint4*)(lo + dst) = *(uint4*)lb;
    }
}

// ---------------- logits GEMM: mma.sync bf16, Markidis 3-pass ----------------
// C[4096,32000] = A[4096,1024] @ B^T, B stored [V][K].
// CTA 128x128, 8 warps (2x4), warp tile 64x32. K-chunk 64, cp.async 2-stage.
// smem arrays per stage: Ah, Al, Bh, Bl = 128 rows x 72 bf16 (144B stride).
#define ROWB   144
#define ARR_SZ (128 * ROWB)          // 18432 B
#define STAGE  (4 * ARR_SZ)          // 73728 B
#define SM_TOT (2 * STAGE)           // 147456 B

__global__ __launch_bounds__(256, 1) void logits_mma_kernel(
    const __nv_bfloat16* __restrict__ Ah, const __nv_bfloat16* __restrict__ Al,
    const __nv_bfloat16* __restrict__ Bh, const __nv_bfloat16* __restrict__ Bl,
    const float* __restrict__ bias, float* __restrict__ C) {
    extern __shared__ __align__(128) char smem[];
    uint32_t sb = smem_u32(smem);

    int tid = threadIdx.x;
    int wid = tid >> 5, lane = tid & 31;
    int wm = wid & 1, wn = wid >> 1;          // warp grid 2 x 4
    int m0 = blockIdx.x * 128;                // m fast -> B reuse in L2
    int n0 = blockIdx.y * 128;

    // per-thread ldmatrix row offsets (bytes)
    uint32_t a_off = (uint32_t)((wm * 64 + (lane & 15)) * ROWB + (lane >> 4) * 16);
    int l15 = lane & 15;
    uint32_t b_off = (uint32_t)((wn * 32 + (l15 & 7)) * ROWB + (l15 >> 3) * 16);

    const __nv_bfloat16* gsrc[4] = {Ah, Al, Bh, Bl};

    float Cacc[4][4][4];
#pragma unroll
    for (int i = 0; i < 4; i++)
#pragma unroll
        for (int j = 0; j < 4; j++)
#pragma unroll
            for (int k = 0; k < 4; k++) Cacc[i][j][k] = 0.f;

    // ---- stage loader: 4096 x 16B chunks ----
    auto load_stage = [&](int ch, int buf) {
        uint32_t base = sb + buf * STAGE;
        int k0 = ch * 64;
#pragma unroll
        for (int it = 0; it < 16; it++) {
            int i = tid + it * 256;
            int arr = i >> 10, rem = i & 1023;
            int r = rem >> 3, c = rem & 7;
            uint32_t dst = base + arr * ARR_SZ + r * ROWB + c * 16;
            int grow = (arr < 2 ? m0 : n0) + r;
            const __nv_bfloat16* src =
                gsrc[arr] + ((size_t)grow << 10) + k0 + c * 8;
            CP16(dst, src);
        }
    };

    load_stage(0, 0);
    CP_COMMIT();

    for (int ch = 0; ch < 16; ch++) {
        int buf = ch & 1;
        if (ch < 15) {
            load_stage(ch + 1, buf ^ 1);
            CP_COMMIT();
            CP_WAIT(1);
        } else {
            CP_WAIT(0);
        }
        __syncthreads();

        uint32_t sA  = sb + buf * STAGE;
        uint32_t sAl = sA + ARR_SZ;
        uint32_t sB  = sA + 2 * ARR_SZ;
        uint32_t sBl = sA + 3 * ARR_SZ;

#pragma unroll
        for (int ks = 0; ks < 4; ks++) {
            uint32_t ah[4][4], al[4][4], bh[4][2], bl[4][2];
#pragma unroll
            for (int mt = 0; mt < 4; mt++) {
                ldsm4(ah[mt], sA  + mt * (16 * ROWB) + ks * 32 + a_off);
                ldsm4(al[mt], sAl + mt * (16 * ROWB) + ks * 32 + a_off);
            }
#pragma unroll
            for (int nt = 0; nt < 4; nt++) {
                ldsm2(bh[nt], sB  + nt * (8 * ROWB) + ks * 32 + b_off);
                ldsm2(bl[nt], sBl + nt * (8 * ROWB) + ks * 32 + b_off);
            }
#pragma unroll
            for (int mt = 0; mt < 4; mt++)
#pragma unroll
                for (int nt = 0; nt < 4; nt++) {
                    mma_bf16(Cacc[mt][nt], ah[mt], bh[nt]);
                    mma_bf16(Cacc[mt][nt], ah[mt], bl[nt]);
                    mma_bf16(Cacc[mt][nt], al[mt], bh[nt]);
                }
        }
        __syncthreads();
    }

    // ---- epilogue ----
    int row0 = m0 + wm * 64;
    int col0 = n0 + wn * 32;
#pragma unroll
    for (int mt = 0; mt < 4; mt++) {
#pragma unroll
        for (int nt = 0; nt < 4; nt++) {
            int r = row0 + mt * 16 + (lane >> 2);
            int cn = col0 + nt * 8 + 2 * (lane & 3);
            float b0 = bias[cn], b1 = bias[cn + 1];
            float* p0 = C + (size_t)r * Vv + cn;
            p0[0] = Cacc[mt][nt][0] + b0;
            p0[1] = Cacc[mt][nt][1] + b1;
            float* p1 = C + (size_t)(r + 8) * Vv + cn;
            p1[0] = Cacc[mt][nt][2] + b0;
            p1[1] = Cacc[mt][nt][3] + b1;
        }
    }
}

// ---------------- launch -----------------------------------------------------
extern "C" void kernel_launch(void* const* d_in, const int* in_sizes, int n_in,
                              void* d_out, int out_size) {
    (void)in_sizes; (void)n_in; (void)out_size;
    const int*   inp = (const int*)d_in[0];
    const float* tok = (const float*)d_in[1];
    const float* pos = (const float*)d_in[2];
    const float* Wk  = (const float*)d_in[3];
    const float* Wq  = (const float*)d_in[4];
    const float* Wv  = (const float*)d_in[5];
    const float* ffW = (const float*)d_in[6];
    const float* ffb = (const float*)d_in[7];
    const float* oW  = (const float*)d_in[8];
    const float* ob  = (const float*)d_in[9];
    float* out = (float*)d_out;

    void *pz = nullptr, *pf = nullptr;
    void *pah = nullptr, *pal = nullptr, *pbh = nullptr, *pbl = nullptr;
    cudaGetSymbolAddress(&pz, g_z);
    cudaGetSymbolAddress(&pf, g_f);
    cudaGetSymbolAddress(&pah, g_Ahi);
    cudaGetSymbolAddress(&pal, g_Alo);
    cudaGetSymbolAddress(&pbh, g_Bhi);
    cudaGetSymbolAddress(&pbl, g_Blo);

    embed_kernel<<<Mm, 256>>>(inp, tok, pos);
    qkv_kernel<<<dim3(Mm / 128, Hh, 3), 256>>>(Wk, Wq, Wv);

    size_t smem = (size_t)(64 * 64 + 64 * 65 + 64 * 64 + 64 * 64) * sizeof(float);
    cudaFuncSetAttribute(attn_kernel, cudaFuncAttributeMaxDynamicSharedMemorySize,
                         (int)smem);
    attn_kernel<<<dim3(Bb * Hh, Tt / 64), 256, smem>>>();

    sgemm_kernel<true><<<dim3(Ee / 128, Mm / 128), 256>>>(
        (const float*)pz, ffW, ffb, (float*)pf, Ee);

    // B-split can run concurrently with everything before the logits GEMM
    cvt_transpose_kernel<<<dim3(Vv / 64, Ee / 64), 256>>>(
        oW, (__nv_bfloat16*)pbh, (__nv_bfloat16*)pbl);
    cvt_split_kernel<<<(Mm * Ee / 4) / 256, 256>>>(
        (const float*)pf, (__nv_bfloat16*)pah, (__nv_bfloat16*)pal);

    cudaFuncSetAttribute(logits_mma_kernel,
                         cudaFuncAttributeMaxDynamicSharedMemorySize, SM_TOT);
    logits_mma_kernel<<<dim3(Mm / 128, Vv / 128), 256, SM_TOT>>>(
        (const __nv_bfloat16*)pah, (const __nv_bfloat16*)pal,
        (const __nv_bfloat16*)pbh, (const __nv_bfloat16*)pbl, ob, out);
}

// round 4
// speedup vs baseline: 2.4185x; 1.1680x over previous
#include <cuda_runtime.h>
#include <cuda_bf16.h>
#include <cstdint>

#define Bb 4
#define Tt 1024
#define Vv 32000
#define Ee 1024
#define Hh 16
#define HSs 64
#define Mm 4096  // B*T

// ---------------- scratch (static device globals) ---------------------------
__device__ __nv_bfloat16 g_xh[(size_t)Mm * Ee];    // embedded input hi/lo
__device__ __nv_bfloat16 g_xl[(size_t)Mm * Ee];
__device__ __nv_bfloat16 g_Wh[(size_t)3 * Ee * Ee];  // qkv weights [3][N=h*64+d][K=e]
__device__ __nv_bfloat16 g_Wl[(size_t)3 * Ee * Ee];
__device__ float g_k[(size_t)Bb * Hh * Tt * HSs];
__device__ float g_q[(size_t)Bb * Hh * Tt * HSs];
__device__ float g_v[(size_t)Bb * Hh * Tt * HSs];
__device__ __nv_bfloat16 g_zh[(size_t)Mm * Ee];    // attention out hi/lo
__device__ __nv_bfloat16 g_zl[(size_t)Mm * Ee];
__device__ __nv_bfloat16 g_Fh[(size_t)Ee * Ee];    // ffW^T hi/lo  [N][K]
__device__ __nv_bfloat16 g_Fl[(size_t)Ee * Ee];
__device__ __nv_bfloat16 g_Ahi[(size_t)Mm * Ee];   // FF out hi/lo (logits A)
__device__ __nv_bfloat16 g_Alo[(size_t)Mm * Ee];
__device__ __nv_bfloat16 g_Bhi[(size_t)Vv * Ee];   // out_W^T hi/lo [V][K]
__device__ __nv_bfloat16 g_Blo[(size_t)Vv * Ee];

// ===================== arch-neutral PTX helpers (sm_80+) ====================
__device__ __forceinline__ uint32_t smem_u32(const void* p) {
    uint32_t a;
    asm("{ .reg .u64 t; cvta.to.shared.u64 t, %1; cvt.u32.u64 %0, t; }"
        : "=r"(a) : "l"(p));
    return a;
}
__device__ __forceinline__ void ldsm4(uint32_t* r, uint32_t addr) {
    asm volatile("ldmatrix.sync.aligned.m8n8.x4.shared.b16 {%0,%1,%2,%3}, [%4];"
                 : "=r"(r[0]), "=r"(r[1]), "=r"(r[2]), "=r"(r[3]) : "r"(addr));
}
__device__ __forceinline__ void ldsm2(uint32_t* r, uint32_t addr) {
    asm volatile("ldmatrix.sync.aligned.m8n8.x2.shared.b16 {%0,%1}, [%2];"
                 : "=r"(r[0]), "=r"(r[1]) : "r"(addr));
}
__device__ __forceinline__ void mma_bf16(float* c, const uint32_t* a,
                                         const uint32_t* b) {
    asm volatile(
        "mma.sync.aligned.m16n8k16.row.col.f32.bf16.bf16.f32 "
        "{%0,%1,%2,%3}, {%4,%5,%6,%7}, {%8,%9}, {%0,%1,%2,%3};"
        : "+f"(c[0]), "+f"(c[1]), "+f"(c[2]), "+f"(c[3])
        : "r"(a[0]), "r"(a[1]), "r"(a[2]), "r"(a[3]), "r"(b[0]), "r"(b[1]));
}
#define CP16(dst, src) \
    asm volatile("cp.async.cg.shared.global [%0], [%1], 16;" \
                 :: "r"(dst), "l"(src))
#define CP_COMMIT() asm volatile("cp.async.commit_group;" ::: "memory")
#define CP_WAIT(n)  asm volatile("cp.async.wait_group %0;" :: "n"(n) : "memory")

__device__ __forceinline__ void split2(float v, __nv_bfloat16& h, __nv_bfloat16& l) {
    h = __float2bfloat16(v);
    l = __float2bfloat16(v - __bfloat162float(h));
}

// ---------------- embed: x = tok_emb[inputs] + pos_emb, split hi/lo ----------
__global__ void embed_kernel(const int* __restrict__ inp,
                             const float* __restrict__ tok,
                             const float* __restrict__ pos) {
    int row = blockIdx.x;
    int t   = row & (Tt - 1);
    int id  = inp[row];
    const float4* te = (const float4*)(tok + (size_t)id * Ee);
    const float4* pe = (const float4*)(pos + (size_t)t * Ee);
    int i = threadIdx.x;
    float4 a = te[i], b = pe[i];
    float x[4] = {a.x + b.x, a.y + b.y, a.z + b.z, a.w + b.w};
    __align__(8) __nv_bfloat16 h[4], l[4];
#pragma unroll
    for (int j = 0; j < 4; j++) split2(x[j], h[j], l[j]);
    size_t o = ((size_t)row << 10) + i * 4;
    *(uint2*)(g_xh + o) = *(uint2*)h;
    *(uint2*)(g_xl + o) = *(uint2*)l;
}

// ---------------- QKV weights: [H][E][HS] -> [h*64+d][e] bf16 hi/lo ---------
__global__ void wsplit_kernel(const float* __restrict__ Wk,
                              const float* __restrict__ Wq,
                              const float* __restrict__ Wv) {
    __shared__ float tile[64][65];
    int z = blockIdx.z;
    const float* W = (z == 0) ? Wk : (z == 1) ? Wq : Wv;
    int h  = blockIdx.x;       // head
    int eb = blockIdx.y * 64;  // e block
    int tid = threadIdx.x;

    const float* Wh = W + (size_t)h * Ee * HSs;
    for (int i = tid; i < 1024; i += 256) {
        int r = i >> 4, c4 = i & 15;   // r = e row, c4*4 = d col
        float4 v = *(const float4*)(Wh + (size_t)(eb + r) * HSs + c4 * 4);
        tile[c4 * 4 + 0][r] = v.x;
        tile[c4 * 4 + 1][r] = v.y;
        tile[c4 * 4 + 2][r] = v.z;
        tile[c4 * 4 + 3][r] = v.w;
    }
    __syncthreads();

    __nv_bfloat16* oh = g_Wh + (size_t)z * Ee * Ee;
    __nv_bfloat16* ol = g_Wl + (size_t)z * Ee * Ee;
    for (int i = tid; i < 512; i += 256) {
        int d = i >> 3, c = i & 7;
        __align__(16) __nv_bfloat16 hb[8], lb[8];
#pragma unroll
        for (int j = 0; j < 8; j++) split2(tile[d][c * 8 + j], hb[j], lb[j]);
        size_t dst = (size_t)(h * 64 + d) * Ee + eb + c * 8;
        *(uint4*)(oh + dst) = *(uint4*)hb;
        *(uint4*)(ol + dst) = *(uint4*)lb;
    }
}

// ---------------- generic [K][N] fp32 -> [N][K] bf16 hi/lo transpose ---------
__global__ void cvt_transpose_kernel(const float* __restrict__ W,
                                     __nv_bfloat16* __restrict__ hi,
                                     __nv_bfloat16* __restrict__ lo, int N) {
    __shared__ float tile[64][65];
    int nb = blockIdx.x * 64;
    int kb = blockIdx.y * 64;
    int tid = threadIdx.x;

    for (int i = tid; i < 1024; i += 256) {
        int r = i >> 4, c4 = i & 15;
        float4 v = *(const float4*)(W + (size_t)(kb + r) * N + nb + c4 * 4);
        tile[c4 * 4 + 0][r] = v.x;
        tile[c4 * 4 + 1][r] = v.y;
        tile[c4 * 4 + 2][r] = v.z;
        tile[c4 * 4 + 3][r] = v.w;
    }
    __syncthreads();

    for (int i = tid; i < 512; i += 256) {
        int nr = i >> 3, c = i & 7;
        __align__(16) __nv_bfloat16 hb[8], lb[8];
#pragma unroll
        for (int j = 0; j < 8; j++) split2(tile[nr][c * 8 + j], hb[j], lb[j]);
        size_t dst = (size_t)(nb + nr) * Ee + kb + c * 8;
        *(uint4*)(hi + dst) = *(uint4*)hb;
        *(uint4*)(lo + dst) = *(uint4*)lb;
    }
}

// ---------------- flash attention (fp32, split epilogue) ---------------------
__global__ void attn_kernel() {
    extern __shared__ __align__(16) float sm[];
    float* Qs  = sm;
    float* KsT = Qs + 64 * 64;
    float* Vs  = KsT + 64 * 65;
    float* Ps  = Vs + 64 * 64;

    int bh = blockIdx.x;
    int rt = blockIdx.y;
    const float* Qb = g_k + (size_t)bh * Tt * HSs;
    const float* Kb = g_q + (size_t)bh * Tt * HSs;
    const float* Vb = g_v + (size_t)bh * Tt * HSs;

    int tid = threadIdx.x;
    int ty = tid >> 4, tx = tid & 15;

    for (int i = tid; i < 1024; i += 256) {
        int r = i >> 4, c4 = i & 15;
        *(float4*)&Qs[r * 64 + c4 * 4] =
            *(const float4*)(Qb + (size_t)(rt * 64 + r) * 64 + c4 * 4);
    }

    float mr[4], lr[4], O[4][4];
#pragma unroll
    for (int i = 0; i < 4; i++) {
        mr[i] = -1e30f; lr[i] = 0.f;
#pragma unroll
        for (int j = 0; j < 4; j++) O[i][j] = 0.f;
    }

    const unsigned FULL = 0xffffffffu;
    const float scl = 0.125f;

    for (int st = 0; st <= rt; st++) {
        for (int i = tid; i < 1024; i += 256) {
            int r = i >> 4, c4 = i & 15;
            float4 kv = *(const float4*)(Kb + (size_t)(st * 64 + r) * 64 + c4 * 4);
            KsT[(c4 * 4 + 0) * 65 + r] = kv.x;
            KsT[(c4 * 4 + 1) * 65 + r] = kv.y;
            KsT[(c4 * 4 + 2) * 65 + r] = kv.z;
            KsT[(c4 * 4 + 3) * 65 + r] = kv.w;
            *(float4*)&Vs[r * 64 + c4 * 4] =
                *(const float4*)(Vb + (size_t)(st * 64 + r) * 64 + c4 * 4);
        }
        __syncthreads();

        float S[4][4];
#pragma unroll
        for (int i = 0; i < 4; i++)
#pragma unroll
            for (int j = 0; j < 4; j++) S[i][j] = 0.f;

#pragma unroll 16
        for (int kk = 0; kk < 64; kk++) {
            float a[4], bb[4];
#pragma unroll
            for (int i = 0; i < 4; i++) a[i] = Qs[(ty * 4 + i) * 64 + kk];
#pragma unroll
            for (int j = 0; j < 4; j++) bb[j] = KsT[kk * 65 + tx * 4 + j];
#pragma unroll
            for (int i = 0; i < 4; i++)
#pragma unroll
                for (int j = 0; j < 4; j++) S[i][j] += a[i] * bb[j];
        }

#pragma unroll
        for (int i = 0; i < 4; i++)
#pragma unroll
            for (int j = 0; j < 4; j++) {
                float s = S[i][j] * scl;
                if (st == rt && (tx * 4 + j) > (ty * 4 + i)) s = -1e30f;
                S[i][j] = s;
            }

#pragma unroll
        for (int i = 0; i < 4; i++) {
            float rm = fmaxf(fmaxf(S[i][0], S[i][1]), fmaxf(S[i][2], S[i][3]));
#pragma unroll
            for (int o = 1; o < 16; o <<= 1)
                rm = fmaxf(rm, __shfl_xor_sync(FULL, rm, o));
            float nm = fmaxf(mr[i], rm);
            float alpha = __expf(mr[i] - nm);
            float rs = 0.f;
#pragma unroll
            for (int j = 0; j < 4; j++) {
                S[i][j] = __expf(S[i][j] - nm);
                rs += S[i][j];
            }
#pragma unroll
            for (int o = 1; o < 16; o <<= 1)
                rs += __shfl_xor_sync(FULL, rs, o);
            lr[i] = lr[i] * alpha + rs;
            mr[i] = nm;
#pragma unroll
            for (int j = 0; j < 4; j++) O[i][j] *= alpha;
        }

#pragma unroll
        for (int i = 0; i < 4; i++)
            *(float4*)&Ps[(ty * 4 + i) * 64 + tx * 4] =
                make_float4(S[i][0], S[i][1], S[i][2], S[i][3]);
        __syncthreads();

#pragma unroll 8
        for (int c = 0; c < 64; c++) {
            float4 vv = *(float4*)&Vs[c * 64 + tx * 4];
#pragma unroll
            for (int i = 0; i < 4; i++) {
                float p = Ps[(ty * 4 + i) * 64 + c];
                O[i][0] += p * vv.x;
                O[i][1] += p * vv.y;
                O[i][2] += p * vv.z;
                O[i][3] += p * vv.w;
            }
        }
        __syncthreads();
    }

    int b = bh >> 4, h = bh & 15;
#pragma unroll
    for (int i = 0; i < 4; i++) {
        int t = rt * 64 + ty * 4 + i;
        float inv = 1.f / lr[i];
        __align__(8) __nv_bfloat16 zh[4], zl[4];
#pragma unroll
        for (int j = 0; j < 4; j++) split2(O[i][j] * inv, zh[j], zl[j]);
        size_t o = (((size_t)(b * Tt + t)) << 10) + h * HSs + tx * 4;
        *(uint2*)(g_zh + o) = *(uint2*)zh;
        *(uint2*)(g_zl + o) = *(uint2*)zl;
    }
}

// ---------------- Markidis mma GEMM core, templated epilogue -----------------
// C[M, N] = A[M,1024] @ B^T, B stored [N][1024] bf16 hi/lo.
// CTA 128x128, 8 warps (2x4), warp tile 64x32, K-chunk 64, cp.async 2-stage.
// EPI: 0 = logits (bias, fp32 C ldc=Vv)
//      1 = FF (bias+relu, bf16 hi/lo out ldc=Ee)
//      2 = qkv (no bias, fp32 strided [b][h][t][d])
#define ROWB   144
#define ARR_SZ (128 * ROWB)
#define STAGE  (4 * ARR_SZ)
#define SM_TOT (2 * STAGE)

template <int EPI>
__global__ __launch_bounds__(256, 1) void mk_mma_kernel(
    const __nv_bfloat16* __restrict__ Ah, const __nv_bfloat16* __restrict__ Al,
    const __nv_bfloat16* __restrict__ Bh, const __nv_bfloat16* __restrict__ Bl,
    const float* __restrict__ bias, float* __restrict__ C,
    __nv_bfloat16* __restrict__ Ch, __nv_bfloat16* __restrict__ Cl) {
    extern __shared__ __align__(128) char smem[];
    uint32_t sb = smem_u32(smem);

    int tid = threadIdx.x;
    int wid = tid >> 5, lane = tid & 31;
    int wm = wid & 1, wn = wid >> 1;
    int m0 = blockIdx.x * 128;
    int n0 = blockIdx.y * 128;

    uint32_t a_off = (uint32_t)((wm * 64 + (lane & 15)) * ROWB + (lane >> 4) * 16);
    int l15 = lane & 15;
    uint32_t b_off = (uint32_t)((wn * 32 + (l15 & 7)) * ROWB + (l15 >> 3) * 16);

    const __nv_bfloat16* gsrc[4] = {Ah, Al, Bh, Bl};

    float Cacc[4][4][4];
#pragma unroll
    for (int i = 0; i < 4; i++)
#pragma unroll
        for (int j = 0; j < 4; j++)
#pragma unroll
            for (int k = 0; k < 4; k++) Cacc[i][j][k] = 0.f;

    auto load_stage = [&](int ch, int buf) {
        uint32_t base = sb + buf * STAGE;
        int k0 = ch * 64;
#pragma unroll
        for (int it = 0; it < 16; it++) {
            int i = tid + it * 256;
            int arr = i >> 10, rem = i & 1023;
            int r = rem >> 3, c = rem & 7;
            uint32_t dst = base + arr * ARR_SZ + r * ROWB + c * 16;
            int grow = (arr < 2 ? m0 : n0) + r;
            const __nv_bfloat16* src =
                gsrc[arr] + ((size_t)grow << 10) + k0 + c * 8;
            CP16(dst, src);
        }
    };

    load_stage(0, 0);
    CP_COMMIT();

    for (int ch = 0; ch < 16; ch++) {
        int buf = ch & 1;
        if (ch < 15) {
            load_stage(ch + 1, buf ^ 1);
            CP_COMMIT();
            CP_WAIT(1);
        } else {
            CP_WAIT(0);
        }
        __syncthreads();

        uint32_t sA  = sb + buf * STAGE;
        uint32_t sAl = sA + ARR_SZ;
        uint32_t sB  = sA + 2 * ARR_SZ;
        uint32_t sBl = sA + 3 * ARR_SZ;

#pragma unroll
        for (int ks = 0; ks < 4; ks++) {
            uint32_t ah[4][4], al[4][4], bh[4][2], bl[4][2];
#pragma unroll
            for (int mt = 0; mt < 4; mt++) {
                ldsm4(ah[mt], sA  + mt * (16 * ROWB) + ks * 32 + a_off);
                ldsm4(al[mt], sAl + mt * (16 * ROWB) + ks * 32 + a_off);
            }
#pragma unroll
            for (int nt = 0; nt < 4; nt++) {
                ldsm2(bh[nt], sB  + nt * (8 * ROWB) + ks * 32 + b_off);
                ldsm2(bl[nt], sBl + nt * (8 * ROWB) + ks * 32 + b_off);
            }
#pragma unroll
            for (int mt = 0; mt < 4; mt++)
#pragma unroll
                for (int nt = 0; nt < 4; nt++) {
                    mma_bf16(Cacc[mt][nt], ah[mt], bh[nt]);
                    mma_bf16(Cacc[mt][nt], ah[mt], bl[nt]);
                    mma_bf16(Cacc[mt][nt], al[mt], bh[nt]);
                }
        }
        __syncthreads();
    }

    // ---- epilogue ----
    int row0 = m0 + wm * 64;
    int col0 = n0 + wn * 32;
#pragma unroll
    for (int mt = 0; mt < 4; mt++) {
#pragma unroll
        for (int nt = 0; nt < 4; nt++) {
            int r = row0 + mt * 16 + (lane >> 2);
            int cn = col0 + nt * 8 + 2 * (lane & 3);
            if (EPI == 0) {
                float b0 = bias[cn], b1 = bias[cn + 1];
                float* p0 = C + (size_t)r * Vv + cn;
                p0[0] = Cacc[mt][nt][0] + b0;
                p0[1] = Cacc[mt][nt][1] + b1;
                float* p1 = C + (size_t)(r + 8) * Vv + cn;
                p1[0] = Cacc[mt][nt][2] + b0;
                p1[1] = Cacc[mt][nt][3] + b1;
            } else if (EPI == 1) {
                float b0 = bias[cn], b1 = bias[cn + 1];
#pragma unroll
                for (int hh = 0; hh < 2; hh++) {
                    float v0 = fmaxf(Cacc[mt][nt][hh * 2 + 0] + b0, 0.f);
                    float v1 = fmaxf(Cacc[mt][nt][hh * 2 + 1] + b1, 0.f);
                    __align__(4) __nv_bfloat16 ph[2], pl[2];
                    split2(v0, ph[0], pl[0]);
                    split2(v1, ph[1], pl[1]);
                    size_t o = ((size_t)(r + hh * 8) << 10) + cn;
                    *(uint32_t*)(Ch + o) = *(uint32_t*)ph;
                    *(uint32_t*)(Cl + o) = *(uint32_t*)pl;
                }
            } else {  // qkv: [b][h][t][d]
#pragma unroll
                for (int hh = 0; hh < 2; hh++) {
                    int m = r + hh * 8;
                    size_t o = (size_t)(m >> 10) * (Hh * Tt * HSs) +
                               (size_t)(cn >> 6) * (Tt * HSs) +
                               (size_t)(m & 1023) * HSs + (cn & 63);
                    float2 v = make_float2(Cacc[mt][nt][hh * 2 + 0],
                                           Cacc[mt][nt][hh * 2 + 1]);
                    *(float2*)(C + o) = v;
                }
            }
        }
    }
}

// ---------------- launch -----------------------------------------------------
extern "C" void kernel_launch(void* const* d_in, const int* in_sizes, int n_in,
                              void* d_out, int out_size) {
    (void)in_sizes; (void)n_in; (void)out_size;
    const int*   inp = (const int*)d_in[0];
    const float* tok = (const float*)d_in[1];
    const float* pos = (const float*)d_in[2];
    const float* Wk  = (const float*)d_in[3];
    const float* Wq  = (const float*)d_in[4];
    const float* Wv  = (const float*)d_in[5];
    const float* ffW = (const float*)d_in[6];
    const float* ffb = (const float*)d_in[7];
    const float* oW  = (const float*)d_in[8];
    const float* ob  = (const float*)d_in[9];
    float* out = (float*)d_out;

    void *pxh, *pxl, *pwh, *pwl, *pk, *pq, *pv, *pzh, *pzl;
    void *pfh, *pfl, *pah, *pal, *pbh, *pbl;
    cudaGetSymbolAddress(&pxh, g_xh);  cudaGetSymbolAddress(&pxl, g_xl);
    cudaGetSymbolAddress(&pwh, g_Wh);  cudaGetSymbolAddress(&pwl, g_Wl);
    cudaGetSymbolAddress(&pk, g_k);    cudaGetSymbolAddress(&pq, g_q);
    cudaGetSymbolAddress(&pv, g_v);
    cudaGetSymbolAddress(&pzh, g_zh);  cudaGetSymbolAddress(&pzl, g_zl);
    cudaGetSymbolAddress(&pfh, g_Fh);  cudaGetSymbolAddress(&pfl, g_Fl);
    cudaGetSymbolAddress(&pah, g_Ahi); cudaGetSymbolAddress(&pal, g_Alo);
    cudaGetSymbolAddress(&pbh, g_Bhi); cudaGetSymbolAddress(&pbl, g_Blo);

    cudaFuncSetAttribute(mk_mma_kernel<0>,
                         cudaFuncAttributeMaxDynamicSharedMemorySize, SM_TOT);
    cudaFuncSetAttribute(mk_mma_kernel<1>,
                         cudaFuncAttributeMaxDynamicSharedMemorySize, SM_TOT);
    cudaFuncSetAttribute(mk_mma_kernel<2>,
                         cudaFuncAttributeMaxDynamicSharedMemorySize, SM_TOT);

    embed_kernel<<<Mm, 256>>>(inp, tok, pos);
    wsplit_kernel<<<dim3(Hh, Ee / 64, 3), 256>>>(Wk, Wq, Wv);

    // QKV GEMMs: M=4096, N=1024
    float* qkv_out[3] = {(float*)pk, (float*)pq, (float*)pv};
    for (int z = 0; z < 3; z++) {
        const __nv_bfloat16* bh = (const __nv_bfloat16*)pwh + (size_t)z * Ee * Ee;
        const __nv_bfloat16* bl = (const __nv_bfloat16*)pwl + (size_t)z * Ee * Ee;
        mk_mma_kernel<2><<<dim3(Mm / 128, Ee / 128), 256, SM_TOT>>>(
            (const __nv_bfloat16*)pxh, (const __nv_bfloat16*)pxl, bh, bl,
            nullptr, qkv_out[z], nullptr, nullptr);
    }

    size_t smem = (size_t)(64 * 64 + 64 * 65 + 64 * 64 + 64 * 64) * sizeof(float);
    cudaFuncSetAttribute(attn_kernel, cudaFuncAttributeMaxDynamicSharedMemorySize,
                         (int)smem);
    attn_kernel<<<dim3(Bb * Hh, Tt / 64), 256, smem>>>();

    // FF: transpose+split ffW, then GEMM with relu+split epilogue
    cvt_transpose_kernel<<<dim3(Ee / 64, Ee / 64), 256>>>(
        ffW, (__nv_bfloat16*)pfh, (__nv_bfloat16*)pfl, Ee);
    mk_mma_kernel<1><<<dim3(Mm / 128, Ee / 128), 256, SM_TOT>>>(
        (const __nv_bfloat16*)pzh, (const __nv_bfloat16*)pzl,
        (const __nv_bfloat16*)pfh, (const __nv_bfloat16*)pfl,
        ffb, nullptr, (__nv_bfloat16*)pah, (__nv_bfloat16*)pal);

    // logits
    cvt_transpose_kernel<<<dim3(Vv / 64, Ee / 64), 256>>>(
        oW, (__nv_bfloat16*)pbh, (__nv_bfloat16*)pbl, Vv);
    mk_mma_kernel<0><<<dim3(Mm / 128, Vv / 128), 256, SM_TOT>>>(
        (const __nv_bfloat16*)pah, (const __nv_bfloat16*)pal,
        (const __nv_bfloat16*)pbh, (const __nv_bfloat16*)pbl,
        ob, out, nullptr, nullptr);
}

// round 5
// speedup vs baseline: 2.5842x; 1.0685x over previous
#include <cuda_runtime.h>
#include <cuda_bf16.h>
#include <cstdint>

#define Bb 4
#define Tt 1024
#define Vv 32000
#define Ee 1024
#define Hh 16
#define HSs 64
#define Mm 4096  // B*T
#define KQV_SZ ((size_t)Bb * Hh * Tt * HSs)  // 4194304

// ---------------- scratch (static device globals) ---------------------------
__device__ __nv_bfloat16 g_xh[(size_t)Mm * Ee];
__device__ __nv_bfloat16 g_xl[(size_t)Mm * Ee];
__device__ __nv_bfloat16 g_Wh[(size_t)3 * Ee * Ee];  // [n=z*1024+h*64+d][e]
__device__ __nv_bfloat16 g_Wl[(size_t)3 * Ee * Ee];
__device__ float g_kqv[3 * KQV_SZ];                  // k, q, v
__device__ __nv_bfloat16 g_zh[(size_t)Mm * Ee];
__device__ __nv_bfloat16 g_zl[(size_t)Mm * Ee];
__device__ __nv_bfloat16 g_Fh[(size_t)Ee * Ee];
__device__ __nv_bfloat16 g_Fl[(size_t)Ee * Ee];
__device__ __nv_bfloat16 g_Ahi[(size_t)Mm * Ee];
__device__ __nv_bfloat16 g_Alo[(size_t)Mm * Ee];
__device__ __nv_bfloat16 g_Bhi[(size_t)Vv * Ee];
__device__ __nv_bfloat16 g_Blo[(size_t)Vv * Ee];

// ===================== arch-neutral PTX helpers (sm_80+) ====================
__device__ __forceinline__ uint32_t smem_u32(const void* p) {
    uint32_t a;
    asm("{ .reg .u64 t; cvta.to.shared.u64 t, %1; cvt.u32.u64 %0, t; }"
        : "=r"(a) : "l"(p));
    return a;
}
__device__ __forceinline__ void ldsm4(uint32_t* r, uint32_t addr) {
    asm volatile("ldmatrix.sync.aligned.m8n8.x4.shared.b16 {%0,%1,%2,%3}, [%4];"
                 : "=r"(r[0]), "=r"(r[1]), "=r"(r[2]), "=r"(r[3]) : "r"(addr));
}
__device__ __forceinline__ void ldsm2(uint32_t* r, uint32_t addr) {
    asm volatile("ldmatrix.sync.aligned.m8n8.x2.shared.b16 {%0,%1}, [%2];"
                 : "=r"(r[0]), "=r"(r[1]) : "r"(addr));
}
__device__ __forceinline__ void mma_bf16(float* c, const uint32_t* a,
                                         const uint32_t* b) {
    asm volatile(
        "mma.sync.aligned.m16n8k16.row.col.f32.bf16.bf16.f32 "
        "{%0,%1,%2,%3}, {%4,%5,%6,%7}, {%8,%9}, {%0,%1,%2,%3};"
        : "+f"(c[0]), "+f"(c[1]), "+f"(c[2]), "+f"(c[3])
        : "r"(a[0]), "r"(a[1]), "r"(a[2]), "r"(a[3]), "r"(b[0]), "r"(b[1]));
}
#define CP16(dst, src) \
    asm volatile("cp.async.cg.shared.global [%0], [%1], 16;" \
                 :: "r"(dst), "l"(src))
#define CP_COMMIT() asm volatile("cp.async.commit_group;" ::: "memory")
#define CP_WAIT1()  asm volatile("cp.async.wait_group 1;" ::: "memory")
#define CP_WAIT0()  asm volatile("cp.async.wait_group 0;" ::: "memory")

__device__ __forceinline__ void split2(float v, __nv_bfloat16& h, __nv_bfloat16& l) {
    h = __float2bfloat16(v);
    l = __float2bfloat16(v - __bfloat162float(h));
}

// ---------------- embed ------------------------------------------------------
__global__ void embed_kernel(const int* __restrict__ inp,
                             const float* __restrict__ tok,
                             const float* __restrict__ pos) {
    int row = blockIdx.x;
    int t   = row & (Tt - 1);
    int id  = inp[row];
    const float4* te = (const float4*)(tok + (size_t)id * Ee);
    const float4* pe = (const float4*)(pos + (size_t)t * Ee);
    int i = threadIdx.x;
    float4 a = te[i], b = pe[i];
    float x[4] = {a.x + b.x, a.y + b.y, a.z + b.z, a.w + b.w};
    __align__(8) __nv_bfloat16 h[4], l[4];
#pragma unroll
    for (int j = 0; j < 4; j++) split2(x[j], h[j], l[j]);
    size_t o = ((size_t)row << 10) + i * 4;
    *(uint2*)(g_xh + o) = *(uint2*)h;
    *(uint2*)(g_xl + o) = *(uint2*)l;
}

// ---------------- QKV weights: [H][E][HS] -> [z*1024+h*64+d][e] --------------
__global__ void wsplit_kernel(const float* __restrict__ Wk,
                              const float* __restrict__ Wq,
                              const float* __restrict__ Wv) {
    __shared__ float tile[64][65];
    int z = blockIdx.z;
    const float* W = (z == 0) ? Wk : (z == 1) ? Wq : Wv;
    int h  = blockIdx.x;
    int eb = blockIdx.y * 64;
    int tid = threadIdx.x;

    const float* Wh = W + (size_t)h * Ee * HSs;
    for (int i = tid; i < 1024; i += 256) {
        int r = i >> 4, c4 = i & 15;
        float4 v = *(const float4*)(Wh + (size_t)(eb + r) * HSs + c4 * 4);
        tile[c4 * 4 + 0][r] = v.x;
        tile[c4 * 4 + 1][r] = v.y;
        tile[c4 * 4 + 2][r] = v.z;
        tile[c4 * 4 + 3][r] = v.w;
    }
    __syncthreads();

    __nv_bfloat16* oh = g_Wh + (size_t)z * Ee * Ee;
    __nv_bfloat16* ol = g_Wl + (size_t)z * Ee * Ee;
    for (int i = tid; i < 512; i += 256) {
        int d = i >> 3, c = i & 7;
        __align__(16) __nv_bfloat16 hb[8], lb[8];
#pragma unroll
        for (int j = 0; j < 8; j++) split2(tile[d][c * 8 + j], hb[j], lb[j]);
        size_t dst = (size_t)(h * 64 + d) * Ee + eb + c * 8;
        *(uint4*)(oh + dst) = *(uint4*)hb;
        *(uint4*)(ol + dst) = *(uint4*)lb;
    }
}

// ---------------- generic [K][N] fp32 -> [N][K] bf16 hi/lo transpose ---------
__global__ void cvt_transpose_kernel(const float* __restrict__ W,
                                     __nv_bfloat16* __restrict__ hi,
                                     __nv_bfloat16* __restrict__ lo, int N) {
    __shared__ float tile[64][65];
    int nb = blockIdx.x * 64;
    int kb = blockIdx.y * 64;
    int tid = threadIdx.x;

    for (int i = tid; i < 1024; i += 256) {
        int r = i >> 4, c4 = i & 15;
        float4 v = *(const float4*)(W + (size_t)(kb + r) * N + nb + c4 * 4);
        tile[c4 * 4 + 0][r] = v.x;
        tile[c4 * 4 + 1][r] = v.y;
        tile[c4 * 4 + 2][r] = v.z;
        tile[c4 * 4 + 3][r] = v.w;
    }
    __syncthreads();

    for (int i = tid; i < 512; i += 256) {
        int nr = i >> 3, c = i & 7;
        __align__(16) __nv_bfloat16 hb[8], lb[8];
#pragma unroll
        for (int j = 0; j < 8; j++) split2(tile[nr][c * 8 + j], hb[j], lb[j]);
        size_t dst = (size_t)(nb + nr) * Ee + kb + c * 8;
        *(uint4*)(hi + dst) = *(uint4*)hb;
        *(uint4*)(lo + dst) = *(uint4*)lb;
    }
}

// ---------------- flash attention (fp32, split epilogue) ---------------------
__global__ void attn_kernel() {
    extern __shared__ __align__(16) float sm[];
    float* Qs  = sm;
    float* KsT = Qs + 64 * 64;
    float* Vs  = KsT + 64 * 65;
    float* Ps  = Vs + 64 * 64;

    int bh = blockIdx.x;
    int rt = blockIdx.y;
    const float* Qb = g_kqv + 0 * KQV_SZ + (size_t)bh * Tt * HSs;  // k plays Q
    const float* Kb = g_kqv + 1 * KQV_SZ + (size_t)bh * Tt * HSs;  // q plays K
    const float* Vb = g_kqv + 2 * KQV_SZ + (size_t)bh * Tt * HSs;

    int tid = threadIdx.x;
    int ty = tid >> 4, tx = tid & 15;

    for (int i = tid; i < 1024; i += 256) {
        int r = i >> 4, c4 = i & 15;
        *(float4*)&Qs[r * 64 + c4 * 4] =
            *(const float4*)(Qb + (size_t)(rt * 64 + r) * 64 + c4 * 4);
    }

    float mr[4], lr[4], O[4][4];
#pragma unroll
    for (int i = 0; i < 4; i++) {
        mr[i] = -1e30f; lr[i] = 0.f;
#pragma unroll
        for (int j = 0; j < 4; j++) O[i][j] = 0.f;
    }

    const unsigned FULL = 0xffffffffu;
    const float scl = 0.125f;

    for (int st = 0; st <= rt; st++) {
        for (int i = tid; i < 1024; i += 256) {
            int r = i >> 4, c4 = i & 15;
            float4 kv = *(const float4*)(Kb + (size_t)(st * 64 + r) * 64 + c4 * 4);
            KsT[(c4 * 4 + 0) * 65 + r] = kv.x;
            KsT[(c4 * 4 + 1) * 65 + r] = kv.y;
            KsT[(c4 * 4 + 2) * 65 + r] = kv.z;
            KsT[(c4 * 4 + 3) * 65 + r] = kv.w;
            *(float4*)&Vs[r * 64 + c4 * 4] =
                *(const float4*)(Vb + (size_t)(st * 64 + r) * 64 + c4 * 4);
        }
        __syncthreads();

        float S[4][4];
#pragma unroll
        for (int i = 0; i < 4; i++)
#pragma unroll
            for (int j = 0; j < 4; j++) S[i][j] = 0.f;

#pragma unroll 16
        for (int kk = 0; kk < 64; kk++) {
            float a[4], bb[4];
#pragma unroll
            for (int i = 0; i < 4; i++) a[i] = Qs[(ty * 4 + i) * 64 + kk];
#pragma unroll
            for (int j = 0; j < 4; j++) bb[j] = KsT[kk * 65 + tx * 4 + j];
#pragma unroll
            for (int i = 0; i < 4; i++)
#pragma unroll
                for (int j = 0; j < 4; j++) S[i][j] += a[i] * bb[j];
        }

#pragma unroll
        for (int i = 0; i < 4; i++)
#pragma unroll
            for (int j = 0; j < 4; j++) {
                float s = S[i][j] * scl;
                if (st == rt && (tx * 4 + j) > (ty * 4 + i)) s = -1e30f;
                S[i][j] = s;
            }

#pragma unroll
        for (int i = 0; i < 4; i++) {
            float rm = fmaxf(fmaxf(S[i][0], S[i][1]), fmaxf(S[i][2], S[i][3]));
#pragma unroll
            for (int o = 1; o < 16; o <<= 1)
                rm = fmaxf(rm, __shfl_xor_sync(FULL, rm, o));
            float nm = fmaxf(mr[i], rm);
            float alpha = __expf(mr[i] - nm);
            float rs = 0.f;
#pragma unroll
            for (int j = 0; j < 4; j++) {
                S[i][j] = __expf(S[i][j] - nm);
                rs += S[i][j];
            }
#pragma unroll
            for (int o = 1; o < 16; o <<= 1)
                rs += __shfl_xor_sync(FULL, rs, o);
            lr[i] = lr[i] * alpha + rs;
            mr[i] = nm;
#pragma unroll
            for (int j = 0; j < 4; j++) O[i][j] *= alpha;
        }

#pragma unroll
        for (int i = 0; i < 4; i++)
            *(float4*)&Ps[(ty * 4 + i) * 64 + tx * 4] =
                make_float4(S[i][0], S[i][1], S[i][2], S[i][3]);
        __syncthreads();

#pragma unroll 8
        for (int c = 0; c < 64; c++) {
            float4 vv = *(float4*)&Vs[c * 64 + tx * 4];
#pragma unroll
            for (int i = 0; i < 4; i++) {
                float p = Ps[(ty * 4 + i) * 64 + c];
                O[i][0] += p * vv.x;
                O[i][1] += p * vv.y;
                O[i][2] += p * vv.z;
                O[i][3] += p * vv.w;
            }
        }
        __syncthreads();
    }

    int b = bh >> 4, h = bh & 15;
#pragma unroll
    for (int i = 0; i < 4; i++) {
        int t = rt * 64 + ty * 4 + i;
        float inv = 1.f / lr[i];
        __align__(8) __nv_bfloat16 zh[4], zl[4];
#pragma unroll
        for (int j = 0; j < 4; j++) split2(O[i][j] * inv, zh[j], zl[j]);
        size_t o = (((size_t)(b * Tt + t)) << 10) + h * HSs + tx * 4;
        *(uint2*)(g_zh + o) = *(uint2*)zh;
        *(uint2*)(g_zl + o) = *(uint2*)zl;
    }
}

// ---------------- Markidis mma GEMM core, 3-stage, templated epilogue --------
// EPI: 0 = logits (bias, fp32 ldc=Vv); 1 = FF (bias+relu, bf16 hi/lo);
//      2 = qkv packed (no bias, fp32 strided [z][b][h][t][d])
#define ROWB   144
#define ARR_SZ (128 * ROWB)
#define STAGE  (4 * ARR_SZ)          // 73728
#define SM_TOT (3 * STAGE)           // 221184

template <int EPI>
__global__ __launch_bounds__(256, 1) void mk_mma_kernel(
    const __nv_bfloat16* __restrict__ Ah, const __nv_bfloat16* __restrict__ Al,
    const __nv_bfloat16* __restrict__ Bh, const __nv_bfloat16* __restrict__ Bl,
    const float* __restrict__ bias, float* __restrict__ C,
    __nv_bfloat16* __restrict__ Ch, __nv_bfloat16* __restrict__ Cl) {
    extern __shared__ __align__(128) char smem[];
    uint32_t sb = smem_u32(smem);

    int tid = threadIdx.x;
    int wid = tid >> 5, lane = tid & 31;
    int wm = wid & 1, wn = wid >> 1;
    int m0 = blockIdx.x * 128;
    int n0 = blockIdx.y * 128;

    uint32_t a_off = (uint32_t)((wm * 64 + (lane & 15)) * ROWB + (lane >> 4) * 16);
    int l15 = lane & 15;
    uint32_t b_off = (uint32_t)((wn * 32 + (l15 & 7)) * ROWB + (l15 >> 3) * 16);

    const __nv_bfloat16* gsrc[4] = {Ah, Al, Bh, Bl};

    float Cacc[4][4][4];
#pragma unroll
    for (int i = 0; i < 4; i++)
#pragma unroll
        for (int j = 0; j < 4; j++)
#pragma unroll
            for (int k = 0; k < 4; k++) Cacc[i][j][k] = 0.f;

    auto load_stage = [&](int ch, int buf) {
        uint32_t base = sb + buf * STAGE;
        int k0 = ch * 64;
#pragma unroll
        for (int it = 0; it < 16; it++) {
            int i = tid + it * 256;
            int arr = i >> 10, rem = i & 1023;
            int r = rem >> 3, c = rem & 7;
            uint32_t dst = base + arr * ARR_SZ + r * ROWB + c * 16;
            int grow = (arr < 2 ? m0 : n0) + r;
            const __nv_bfloat16* src =
                gsrc[arr] + ((size_t)grow << 10) + k0 + c * 8;
            CP16(dst, src);
        }
    };

    load_stage(0, 0);
    CP_COMMIT();
    load_stage(1, 1);
    CP_COMMIT();

    for (int ch = 0; ch < 16; ch++) {
        if (ch < 15) CP_WAIT1(); else CP_WAIT0();
        __syncthreads();

        int buf = ch % 3;
        uint32_t sA  = sb + buf * STAGE;
        uint32_t sAl = sA + ARR_SZ;
        uint32_t sB  = sA + 2 * ARR_SZ;
        uint32_t sBl = sA + 3 * ARR_SZ;

#pragma unroll
        for (int ks = 0; ks < 4; ks++) {
            uint32_t ah[4][4], al[4][4], bh[4][2], bl[4][2];
#pragma unroll
            for (int mt = 0; mt < 4; mt++) {
                ldsm4(ah[mt], sA  + mt * (16 * ROWB) + ks * 32 + a_off);
                ldsm4(al[mt], sAl + mt * (16 * ROWB) + ks * 32 + a_off);
            }
#pragma unroll
            for (int nt = 0; nt < 4; nt++) {
                ldsm2(bh[nt], sB  + nt * (8 * ROWB) + ks * 32 + b_off);
                ldsm2(bl[nt], sBl + nt * (8 * ROWB) + ks * 32 + b_off);
            }
            // pass-major: 16 independent MMAs between dependent pairs
#pragma unroll
            for (int mt = 0; mt < 4; mt++)
#pragma unroll
                for (int nt = 0; nt < 4; nt++) mma_bf16(Cacc[mt][nt], ah[mt], bh[nt]);
#pragma unroll
            for (int mt = 0; mt < 4; mt++)
#pragma unroll
                for (int nt = 0; nt < 4; nt++) mma_bf16(Cacc[mt][nt], ah[mt], bl[nt]);
#pragma unroll
            for (int mt = 0; mt < 4; mt++)
#pragma unroll
                for (int nt = 0; nt < 4; nt++) mma_bf16(Cacc[mt][nt], al[mt], bh[nt]);
        }

        if (ch + 2 < 16) {
            load_stage(ch + 2, (ch + 2) % 3);
            CP_COMMIT();
        }
    }

    // ---- epilogue ----
    int row0 = m0 + wm * 64;
    int col0 = n0 + wn * 32;
#pragma unroll
    for (int mt = 0; mt < 4; mt++) {
#pragma unroll
        for (int nt = 0; nt < 4; nt++) {
            int r = row0 + mt * 16 + (lane >> 2);
            int cn = col0 + nt * 8 + 2 * (lane & 3);
            if (EPI == 0) {
                float b0 = bias[cn], b1 = bias[cn + 1];
                float* p0 = C + (size_t)r * Vv + cn;
                p0[0] = Cacc[mt][nt][0] + b0;
                p0[1] = Cacc[mt][nt][1] + b1;
                float* p1 = C + (size_t)(r + 8) * Vv + cn;
                p1[0] = Cacc[mt][nt][2] + b0;
                p1[1] = Cacc[mt][nt][3] + b1;
            } else if (EPI == 1) {
                float b0 = bias[cn], b1 = bias[cn + 1];
#pragma unroll
                for (int hh = 0; hh < 2; hh++) {
                    float v0 = fmaxf(Cacc[mt][nt][hh * 2 + 0] + b0, 0.f);
                    float v1 = fmaxf(Cacc[mt][nt][hh * 2 + 1] + b1, 0.f);
                    __align__(4) __nv_bfloat16 ph[2], pl[2];
                    split2(v0, ph[0], pl[0]);
                    split2(v1, ph[1], pl[1]);
                    size_t o = ((size_t)(r + hh * 8) << 10) + cn;
                    *(uint32_t*)(Ch + o) = *(uint32_t*)ph;
                    *(uint32_t*)(Cl + o) = *(uint32_t*)pl;
                }
            } else {  // qkv packed: n = z*1024 + h*64 + d
#pragma unroll
                for (int hh = 0; hh < 2; hh++) {
                    int m = r + hh * 8;
                    int z = cn >> 10, rem = cn & 1023;
                    size_t o = (size_t)z * KQV_SZ +
                               (size_t)(m >> 10) * (Hh * Tt * HSs) +
                               (size_t)(rem >> 6) * (Tt * HSs) +
                               (size_t)(m & 1023) * HSs + (rem & 63);
                    float2 v = make_float2(Cacc[mt][nt][hh * 2 + 0],
                                           Cacc[mt][nt][hh * 2 + 1]);
                    *(float2*)(C + o) = v;
                }
            }
        }
    }
}

// ---------------- launch -----------------------------------------------------
extern "C" void kernel_launch(void* const* d_in, const int* in_sizes, int n_in,
                              void* d_out, int out_size) {
    (void)in_sizes; (void)n_in; (void)out_size;
    const int*   inp = (const int*)d_in[0];
    const float* tok = (const float*)d_in[1];
    const float* pos = (const float*)d_in[2];
    const float* Wk  = (const float*)d_in[3];
    const float* Wq  = (const float*)d_in[4];
    const float* Wv  = (const float*)d_in[5];
    const float* ffW = (const float*)d_in[6];
    const float* ffb = (const float*)d_in[7];
    const float* oW  = (const float*)d_in[8];
    const float* ob  = (const float*)d_in[9];
    float* out = (float*)d_out;

    void *pxh, *pxl, *pwh, *pwl, *pkqv, *pzh, *pzl;
    void *pfh, *pfl, *pah, *pal, *pbh, *pbl;
    cudaGetSymbolAddress(&pxh, g_xh);  cudaGetSymbolAddress(&pxl, g_xl);
    cudaGetSymbolAddress(&pwh, g_Wh);  cudaGetSymbolAddress(&pwl, g_Wl);
    cudaGetSymbolAddress(&pkqv, g_kqv);
    cudaGetSymbolAddress(&pzh, g_zh);  cudaGetSymbolAddress(&pzl, g_zl);
    cudaGetSymbolAddress(&pfh, g_Fh);  cudaGetSymbolAddress(&pfl, g_Fl);
    cudaGetSymbolAddress(&pah, g_Ahi); cudaGetSymbolAddress(&pal, g_Alo);
    cudaGetSymbolAddress(&pbh, g_Bhi); cudaGetSymbolAddress(&pbl, g_Blo);

    cudaFuncSetAttribute(mk_mma_kernel<0>,
                         cudaFuncAttributeMaxDynamicSharedMemorySize, SM_TOT);
    cudaFuncSetAttribute(mk_mma_kernel<1>,
                         cudaFuncAttributeMaxDynamicSharedMemorySize, SM_TOT);
    cudaFuncSetAttribute(mk_mma_kernel<2>,
                         cudaFuncAttributeMaxDynamicSharedMemorySize, SM_TOT);

    embed_kernel<<<Mm, 256>>>(inp, tok, pos);
    wsplit_kernel<<<dim3(Hh, Ee / 64, 3), 256>>>(Wk, Wq, Wv);

    // QKV: one GEMM, M=4096, N=3072 (packed weights)
    mk_mma_kernel<2><<<dim3(Mm / 128, 3 * Ee / 128), 256, SM_TOT>>>(
        (const __nv_bfloat16*)pxh, (const __nv_bfloat16*)pxl,
        (const __nv_bfloat16*)pwh, (const __nv_bfloat16*)pwl,
        nullptr, (float*)pkqv, nullptr, nullptr);

    size_t smem = (size_t)(64 * 64 + 64 * 65 + 64 * 64 + 64 * 64) * sizeof(float);
    cudaFuncSetAttribute(attn_kernel, cudaFuncAttributeMaxDynamicSharedMemorySize,
                         (int)smem);
    attn_kernel<<<dim3(Bb * Hh, Tt / 64), 256, smem>>>();

    cvt_transpose_kernel<<<dim3(Ee / 64, Ee / 64), 256>>>(
        ffW, (__nv_bfloat16*)pfh, (__nv_bfloat16*)pfl, Ee);
    mk_mma_kernel<1><<<dim3(Mm / 128, Ee / 128), 256, SM_TOT>>>(
        (const __nv_bfloat16*)pzh, (const __nv_bfloat16*)pzl,
        (const __nv_bfloat16*)pfh, (const __nv_bfloat16*)pfl,
        ffb, nullptr, (__nv_bfloat16*)pah, (__nv_bfloat16*)pal);

    cvt_transpose_kernel<<<dim3(Vv / 64, Ee / 64), 256>>>(
        oW, (__nv_bfloat16*)pbh, (__nv_bfloat16*)pbl, Vv);
    mk_mma_kernel<0><<<dim3(Mm / 128, Vv / 128), 256, SM_TOT>>>(
        (const __nv_bfloat16*)pah, (const __nv_bfloat16*)pal,
        (const __nv_bfloat16*)pbh, (const __nv_bfloat16*)pbl,
        ob, out, nullptr, nullptr);
}

// round 6
// speedup vs baseline: 2.6278x; 1.0169x over previous
#include <cuda_runtime.h>
#include <cuda_bf16.h>
#include <cstdint>

#define Bb 4
#define Tt 1024
#define Vv 32000
#define Ee 1024
#define Hh 16
#define HSs 64
#define Mm 4096  // B*T
#define KQV_SZ ((size_t)Bb * Hh * Tt * HSs)

// ---------------- scratch (static device globals) ---------------------------
__device__ __nv_bfloat16 g_xh[(size_t)Mm * Ee];
__device__ __nv_bfloat16 g_xl[(size_t)Mm * Ee];
__device__ __nv_bfloat16 g_Wh[(size_t)3 * Ee * Ee];
__device__ __nv_bfloat16 g_Wl[(size_t)3 * Ee * Ee];
__device__ float g_kqv[3 * KQV_SZ];
__device__ __nv_bfloat16 g_zh[(size_t)Mm * Ee];
__device__ __nv_bfloat16 g_zl[(size_t)Mm * Ee];
__device__ __nv_bfloat16 g_Fh[(size_t)Ee * Ee];
__device__ __nv_bfloat16 g_Fl[(size_t)Ee * Ee];
__device__ __nv_bfloat16 g_Ahi[(size_t)Mm * Ee];
__device__ __nv_bfloat16 g_Alo[(size_t)Mm * Ee];
__device__ __nv_bfloat16 g_Bhi[(size_t)Vv * Ee];
__device__ __nv_bfloat16 g_Blo[(size_t)Vv * Ee];

// ===================== arch-neutral PTX helpers (sm_80+) ====================
__device__ __forceinline__ uint32_t smem_u32(const void* p) {
    uint32_t a;
    asm("{ .reg .u64 t; cvta.to.shared.u64 t, %1; cvt.u32.u64 %0, t; }"
        : "=r"(a) : "l"(p));
    return a;
}
__device__ __forceinline__ void ldsm4(uint32_t* r, uint32_t addr) {
    asm volatile("ldmatrix.sync.aligned.m8n8.x4.shared.b16 {%0,%1,%2,%3}, [%4];"
                 : "=r"(r[0]), "=r"(r[1]), "=r"(r[2]), "=r"(r[3]) : "r"(addr));
}
__device__ __forceinline__ void mma_bf16(float* c, const uint32_t* a,
                                         const uint32_t* b) {
    asm volatile(
        "mma.sync.aligned.m16n8k16.row.col.f32.bf16.bf16.f32 "
        "{%0,%1,%2,%3}, {%4,%5,%6,%7}, {%8,%9}, {%0,%1,%2,%3};"
        : "+f"(c[0]), "+f"(c[1]), "+f"(c[2]), "+f"(c[3])
        : "r"(a[0]), "r"(a[1]), "r"(a[2]), "r"(a[3]), "r"(b[0]), "r"(b[1]));
}
#define CP16(dst, src) \
    asm volatile("cp.async.cg.shared.global [%0], [%1], 16;" \
                 :: "r"(dst), "l"(src))
#define CP_COMMIT() asm volatile("cp.async.commit_group;" ::: "memory")
#define CP_WAIT0()  asm volatile("cp.async.wait_group 0;" ::: "memory")

__device__ __forceinline__ void split2(float v, __nv_bfloat16& h, __nv_bfloat16& l) {
    h = __float2bfloat16(v);
    l = __float2bfloat16(v - __bfloat162float(h));
}

// ---------------- embed ------------------------------------------------------
__global__ void embed_kernel(const int* __restrict__ inp,
                             const float* __restrict__ tok,
                             const float* __restrict__ pos) {
    int row = blockIdx.x;
    int t   = row & (Tt - 1);
    int id  = inp[row];
    const float4* te = (const float4*)(tok + (size_t)id * Ee);
    const float4* pe = (const float4*)(pos + (size_t)t * Ee);
    int i = threadIdx.x;
    float4 a = te[i], b = pe[i];
    float x[4] = {a.x + b.x, a.y + b.y, a.z + b.z, a.w + b.w};
    __align__(8) __nv_bfloat16 h[4], l[4];
#pragma unroll
    for (int j = 0; j < 4; j++) split2(x[j], h[j], l[j]);
    size_t o = ((size_t)row << 10) + i * 4;
    *(uint2*)(g_xh + o) = *(uint2*)h;
    *(uint2*)(g_xl + o) = *(uint2*)l;
}

// ---------------- QKV weights -> [z*1024+h*64+d][e] bf16 hi/lo ---------------
__global__ void wsplit_kernel(const float* __restrict__ Wk,
                              const float* __restrict__ Wq,
                              const float* __restrict__ Wv) {
    __shared__ float tile[64][65];
    int z = blockIdx.z;
    const float* W = (z == 0) ? Wk : (z == 1) ? Wq : Wv;
    int h  = blockIdx.x;
    int eb = blockIdx.y * 64;
    int tid = threadIdx.x;

    const float* Wh = W + (size_t)h * Ee * HSs;
    for (int i = tid; i < 1024; i += 256) {
        int r = i >> 4, c4 = i & 15;
        float4 v = *(const float4*)(Wh + (size_t)(eb + r) * HSs + c4 * 4);
        tile[c4 * 4 + 0][r] = v.x;
        tile[c4 * 4 + 1][r] = v.y;
        tile[c4 * 4 + 2][r] = v.z;
        tile[c4 * 4 + 3][r] = v.w;
    }
    __syncthreads();

    __nv_bfloat16* oh = g_Wh + (size_t)z * Ee * Ee;
    __nv_bfloat16* ol = g_Wl + (size_t)z * Ee * Ee;
    for (int i = tid; i < 512; i += 256) {
        int d = i >> 3, c = i & 7;
        __align__(16) __nv_bfloat16 hb[8], lb[8];
#pragma unroll
        for (int j = 0; j < 8; j++) split2(tile[d][c * 8 + j], hb[j], lb[j]);
        size_t dst = (size_t)(h * 64 + d) * Ee + eb + c * 8;
        *(uint4*)(oh + dst) = *(uint4*)hb;
        *(uint4*)(ol + dst) = *(uint4*)lb;
    }
}

// ---------------- generic [K][N] fp32 -> [N][K] bf16 hi/lo transpose ---------
__global__ void cvt_transpose_kernel(const float* __restrict__ W,
                                     __nv_bfloat16* __restrict__ hi,
                                     __nv_bfloat16* __restrict__ lo, int N) {
    __shared__ float tile[64][65];
    int nb = blockIdx.x * 64;
    int kb = blockIdx.y * 64;
    int tid = threadIdx.x;

    for (int i = tid; i < 1024; i += 256) {
        int r = i >> 4, c4 = i & 15;
        float4 v = *(const float4*)(W + (size_t)(kb + r) * N + nb + c4 * 4);
        tile[c4 * 4 + 0][r] = v.x;
        tile[c4 * 4 + 1][r] = v.y;
        tile[c4 * 4 + 2][r] = v.z;
        tile[c4 * 4 + 3][r] = v.w;
    }
    __syncthreads();

    for (int i = tid; i < 512; i += 256) {
        int nr = i >> 3, c = i & 7;
        __align__(16) __nv_bfloat16 hb[8], lb[8];
#pragma unroll
        for (int j = 0; j < 8; j++) split2(tile[nr][c * 8 + j], hb[j], lb[j]);
        size_t dst = (size_t)(nb + nr) * Ee + kb + c * 8;
        *(uint4*)(hi + dst) = *(uint4*)hb;
        *(uint4*)(lo + dst) = *(uint4*)lb;
    }
}

// ---------------- flash attention (fp32) -------------------------------------
#define KST 68  // KsT row stride in floats (16B-aligned float4 slots)
__global__ void attn_kernel() {
    extern __shared__ __align__(16) float sm[];
    float* Qs  = sm;
    float* KsT = Qs + 64 * 64;
    float* Vs  = KsT + 64 * KST;
    float* Ps  = Vs + 64 * 64;

    int bh = blockIdx.x;
    int rt = blockIdx.y;
    const float* Qb = g_kqv + 0 * KQV_SZ + (size_t)bh * Tt * HSs;
    const float* Kb = g_kqv + 1 * KQV_SZ + (size_t)bh * Tt * HSs;
    const float* Vb = g_kqv + 2 * KQV_SZ + (size_t)bh * Tt * HSs;

    int tid = threadIdx.x;
    int ty = tid >> 4, tx = tid & 15;

    for (int i = tid; i < 1024; i += 256) {
        int r = i >> 4, c4 = i & 15;
        *(float4*)&Qs[r * 64 + c4 * 4] =
            *(const float4*)(Qb + (size_t)(rt * 64 + r) * 64 + c4 * 4);
    }

    float mr[4], lr[4], O[4][4];
#pragma unroll
    for (int i = 0; i < 4; i++) {
        mr[i] = -1e30f; lr[i] = 0.f;
#pragma unroll
        for (int j = 0; j < 4; j++) O[i][j] = 0.f;
    }

    const unsigned FULL = 0xffffffffu;
    const float scl = 0.125f;

    for (int st = 0; st <= rt; st++) {
        for (int i = tid; i < 1024; i += 256) {
            int r = i >> 4, c4 = i & 15;
            float4 kv = *(const float4*)(Kb + (size_t)(st * 64 + r) * 64 + c4 * 4);
            KsT[(c4 * 4 + 0) * KST + r] = kv.x;
            KsT[(c4 * 4 + 1) * KST + r] = kv.y;
            KsT[(c4 * 4 + 2) * KST + r] = kv.z;
            KsT[(c4 * 4 + 3) * KST + r] = kv.w;
            *(float4*)&Vs[r * 64 + c4 * 4] =
                *(const float4*)(Vb + (size_t)(st * 64 + r) * 64 + c4 * 4);
        }
        __syncthreads();

        float S[4][4];
#pragma unroll
        for (int i = 0; i < 4; i++)
#pragma unroll
            for (int j = 0; j < 4; j++) S[i][j] = 0.f;

#pragma unroll 16
        for (int kk = 0; kk < 64; kk++) {
            float a[4];
#pragma unroll
            for (int i = 0; i < 4; i++) a[i] = Qs[(ty * 4 + i) * 64 + kk];
            float4 bv = *(float4*)&KsT[kk * KST + tx * 4];
#pragma unroll
            for (int i = 0; i < 4; i++) {
                S[i][0] += a[i] * bv.x;
                S[i][1] += a[i] * bv.y;
                S[i][2] += a[i] * bv.z;
                S[i][3] += a[i] * bv.w;
            }
        }

#pragma unroll
        for (int i = 0; i < 4; i++)
#pragma unroll
            for (int j = 0; j < 4; j++) {
                float s = S[i][j] * scl;
                if (st == rt && (tx * 4 + j) > (ty * 4 + i)) s = -1e30f;
                S[i][j] = s;
            }

#pragma unroll
        for (int i = 0; i < 4; i++) {
            float rm = fmaxf(fmaxf(S[i][0], S[i][1]), fmaxf(S[i][2], S[i][3]));
#pragma unroll
            for (int o = 1; o < 16; o <<= 1)
                rm = fmaxf(rm, __shfl_xor_sync(FULL, rm, o));
            float nm = fmaxf(mr[i], rm);
            float alpha = __expf(mr[i] - nm);
            float rs = 0.f;
#pragma unroll
            for (int j = 0; j < 4; j++) {
                S[i][j] = __expf(S[i][j] - nm);
                rs += S[i][j];
            }
#pragma unroll
            for (int o = 1; o < 16; o <<= 1)
                rs += __shfl_xor_sync(FULL, rs, o);
            lr[i] = lr[i] * alpha + rs;
            mr[i] = nm;
#pragma unroll
            for (int j = 0; j < 4; j++) O[i][j] *= alpha;
        }

#pragma unroll
        for (int i = 0; i < 4; i++)
            *(float4*)&Ps[(ty * 4 + i) * 64 + tx * 4] =
                make_float4(S[i][0], S[i][1], S[i][2], S[i][3]);
        __syncthreads();

#pragma unroll 8
        for (int c = 0; c < 64; c++) {
            float4 vv = *(float4*)&Vs[c * 64 + tx * 4];
#pragma unroll
            for (int i = 0; i < 4; i++) {
                float p = Ps[(ty * 4 + i) * 64 + c];
                O[i][0] += p * vv.x;
                O[i][1] += p * vv.y;
                O[i][2] += p * vv.z;
                O[i][3] += p * vv.w;
            }
        }
        __syncthreads();
    }

    int b = bh >> 4, h = bh & 15;
#pragma unroll
    for (int i = 0; i < 4; i++) {
        int t = rt * 64 + ty * 4 + i;
        float inv = 1.f / lr[i];
        __align__(8) __nv_bfloat16 zh[4], zl[4];
#pragma unroll
        for (int j = 0; j < 4; j++) split2(O[i][j] * inv, zh[j], zl[j]);
        size_t o = (((size_t)(b * Tt + t)) << 10) + h * HSs + tx * 4;
        *(uint2*)(g_zh + o) = *(uint2*)zh;
        *(uint2*)(g_zl + o) = *(uint2*)zl;
    }
}

// ---------------- Markidis mma GEMM: CTA 128x256, 2-stage, 1 sync ------------
// EPI: 0 = logits (bias, fp32 ldc=Vv); 1 = FF (bias+relu, bf16 hi/lo);
//      2 = qkv packed (no bias, fp32 strided [z][b][h][t][d])
#define ROWB   144
#define ARR_A  (128 * ROWB)                  // 18432
#define ARR_B  (256 * ROWB)                  // 36864
#define STAGE  (2 * ARR_A + 2 * ARR_B)       // 110592
#define SM_TOT (2 * STAGE)                   // 221184

template <int EPI>
__global__ __launch_bounds__(256, 1) void mk_mma_kernel(
    const __nv_bfloat16* __restrict__ Ah, const __nv_bfloat16* __restrict__ Al,
    const __nv_bfloat16* __restrict__ Bh, const __nv_bfloat16* __restrict__ Bl,
    const float* __restrict__ bias, float* __restrict__ C,
    __nv_bfloat16* __restrict__ Ch, __nv_bfloat16* __restrict__ Cl) {
    extern __shared__ __align__(128) char smem[];
    uint32_t sb = smem_u32(smem);

    int tid = threadIdx.x;
    int wid = tid >> 5, lane = tid & 31;
    int wm = wid & 1, wn = wid >> 1;   // 2 x 4 warps, warp tile 64m x 64n
    int m0 = blockIdx.x * 128;
    int n0 = blockIdx.y * 256;

    uint32_t a_off = (uint32_t)((wm * 64 + (lane & 15)) * ROWB + (lane >> 4) * 16);
    // B ldsm4 pair addressing: lanes 0-7 m0(k0-7), 8-15 m1(k8-15),
    // 16-23 m2(rows+8,k0-7), 24-31 m3(rows+8,k8-15)
    uint32_t b_off = (uint32_t)((wn * 64 + ((lane >> 4) * 8) + (lane & 7)) * ROWB +
                                ((lane >> 3) & 1) * 16);

    float Cacc[4][8][4];
#pragma unroll
    for (int i = 0; i < 4; i++)
#pragma unroll
        for (int j = 0; j < 8; j++)
#pragma unroll
            for (int k = 0; k < 4; k++) Cacc[i][j][k] = 0.f;

    auto load_stage = [&](int ch, int buf) {
        uint32_t base = sb + buf * STAGE;
        int k0 = ch * 64;
        // A: 2 arrays x 128 rows x 8 chunks = 2048
#pragma unroll
        for (int it = 0; it < 8; it++) {
            int i = tid + it * 256;
            int arr = i >> 10, rem = i & 1023;
            int r = rem >> 3, c = rem & 7;
            uint32_t dst = base + arr * ARR_A + r * ROWB + c * 16;
            const __nv_bfloat16* src =
                (arr == 0 ? Ah : Al) + (((size_t)(m0 + r)) << 10) + k0 + c * 8;
            CP16(dst, src);
        }
        // B: 2 arrays x 256 rows x 8 chunks = 4096
        uint32_t bbase = base + 2 * ARR_A;
#pragma unroll
        for (int it = 0; it < 16; it++) {
            int i = tid + it * 256;
            int arr = i >> 11, rem = i & 2047;
            int r = rem >> 3, c = rem & 7;
            uint32_t dst = bbase + arr * ARR_B + r * ROWB + c * 16;
            const __nv_bfloat16* src =
                (arr == 0 ? Bh : Bl) + (((size_t)(n0 + r)) << 10) + k0 + c * 8;
            CP16(dst, src);
        }
    };

    load_stage(0, 0);
    CP_COMMIT();

    int buf = 0;
    for (int ch = 0; ch < 16; ch++) {
        CP_WAIT0();
        __syncthreads();
        if (ch < 15) {
            load_stage(ch + 1, buf ^ 1);
            CP_COMMIT();
        }

        uint32_t sA  = sb + buf * STAGE;
        uint32_t sAl = sA + ARR_A;
        uint32_t sB  = sA + 2 * ARR_A;
        uint32_t sBl = sB + ARR_B;

#pragma unroll
        for (int ks = 0; ks < 4; ks++) {
            uint32_t ah[4][4], al[4][4], bh[8][2], bl[8][2];
#pragma unroll
            for (int mt = 0; mt < 4; mt++) {
                ldsm4(ah[mt], sA  + mt * (16 * ROWB) + ks * 32 + a_off);
                ldsm4(al[mt], sAl + mt * (16 * ROWB) + ks * 32 + a_off);
            }
#pragma unroll
            for (int p = 0; p < 4; p++) {
                ldsm4(&bh[2 * p][0], sB  + p * (16 * ROWB) + ks * 32 + b_off);
                ldsm4(&bl[2 * p][0], sBl + p * (16 * ROWB) + ks * 32 + b_off);
            }
#pragma unroll
            for (int mt = 0; mt < 4; mt++)
#pragma unroll
                for (int nt = 0; nt < 8; nt++) mma_bf16(Cacc[mt][nt], ah[mt], bh[nt]);
#pragma unroll
            for (int mt = 0; mt < 4; mt++)
#pragma unroll
                for (int nt = 0; nt < 8; nt++) mma_bf16(Cacc[mt][nt], ah[mt], bl[nt]);
#pragma unroll
            for (int mt = 0; mt < 4; mt++)
#pragma unroll
                for (int nt = 0; nt < 8; nt++) mma_bf16(Cacc[mt][nt], al[mt], bh[nt]);
        }
        buf ^= 1;
    }

    // ---- epilogue ----
    int row0 = m0 + wm * 64;
    int col0 = n0 + wn * 64;
#pragma unroll
    for (int mt = 0; mt < 4; mt++) {
#pragma unroll
        for (int nt = 0; nt < 8; nt++) {
            int r = row0 + mt * 16 + (lane >> 2);
            int cn = col0 + nt * 8 + 2 * (lane & 3);
            if (EPI == 0) {
                float b0 = bias[cn], b1 = bias[cn + 1];
                float* p0 = C + (size_t)r * Vv + cn;
                p0[0] = Cacc[mt][nt][0] + b0;
                p0[1] = Cacc[mt][nt][1] + b1;
                float* p1 = C + (size_t)(r + 8) * Vv + cn;
                p1[0] = Cacc[mt][nt][2] + b0;
                p1[1] = Cacc[mt][nt][3] + b1;
            } else if (EPI == 1) {
                float b0 = bias[cn], b1 = bias[cn + 1];
#pragma unroll
                for (int hh = 0; hh < 2; hh++) {
                    float v0 = fmaxf(Cacc[mt][nt][hh * 2 + 0] + b0, 0.f);
                    float v1 = fmaxf(Cacc[mt][nt][hh * 2 + 1] + b1, 0.f);
                    __align__(4) __nv_bfloat16 ph[2], pl[2];
                    split2(v0, ph[0], pl[0]);
                    split2(v1, ph[1], pl[1]);
                    size_t o = ((size_t)(r + hh * 8) << 10) + cn;
                    *(uint32_t*)(Ch + o) = *(uint32_t*)ph;
                    *(uint32_t*)(Cl + o) = *(uint32_t*)pl;
                }
            } else {  // qkv packed: n = z*1024 + h*64 + d
#pragma unroll
                for (int hh = 0; hh < 2; hh++) {
                    int m = r + hh * 8;
                    int z = cn >> 10, rem = cn & 1023;
                    size_t o = (size_t)z * KQV_SZ +
                               (size_t)(m >> 10) * (Hh * Tt * HSs) +
                               (size_t)(rem >> 6) * (Tt * HSs) +
                               (size_t)(m & 1023) * HSs + (rem & 63);
                    float2 v = make_float2(Cacc[mt][nt][hh * 2 + 0],
                                           Cacc[mt][nt][hh * 2 + 1]);
                    *(float2*)(C + o) = v;
                }
            }
        }
    }
}

// ---------------- launch -----------------------------------------------------
extern "C" void kernel_launch(void* const* d_in, const int* in_sizes, int n_in,
                              void* d_out, int out_size) {
    (void)in_sizes; (void)n_in; (void)out_size;
    const int*   inp = (const int*)d_in[0];
    const float* tok = (const float*)d_in[1];
    const float* pos = (const float*)d_in[2];
    const float* Wk  = (const float*)d_in[3];
    const float* Wq  = (const float*)d_in[4];
    const float* Wv  = (const float*)d_in[5];
    const float* ffW = (const float*)d_in[6];
    const float* ffb = (const float*)d_in[7];
    const float* oW  = (const float*)d_in[8];
    const float* ob  = (const float*)d_in[9];
    float* out = (float*)d_out;

    void *pxh, *pxl, *pwh, *pwl, *pkqv, *pzh, *pzl;
    void *pfh, *pfl, *pah, *pal, *pbh, *pbl;
    cudaGetSymbolAddress(&pxh, g_xh);  cudaGetSymbolAddress(&pxl, g_xl);
    cudaGetSymbolAddress(&pwh, g_Wh);  cudaGetSymbolAddress(&pwl, g_Wl);
    cudaGetSymbolAddress(&pkqv, g_kqv);
    cudaGetSymbolAddress(&pzh, g_zh);  cudaGetSymbolAddress(&pzl, g_zl);
    cudaGetSymbolAddress(&pfh, g_Fh);  cudaGetSymbolAddress(&pfl, g_Fl);
    cudaGetSymbolAddress(&pah, g_Ahi); cudaGetSymbolAddress(&pal, g_Alo);
    cudaGetSymbolAddress(&pbh, g_Bhi); cudaGetSymbolAddress(&pbl, g_Blo);

    cudaFuncSetAttribute(mk_mma_kernel<0>,
                         cudaFuncAttributeMaxDynamicSharedMemorySize, SM_TOT);
    cudaFuncSetAttribute(mk_mma_kernel<1>,
                         cudaFuncAttributeMaxDynamicSharedMemorySize, SM_TOT);
    cudaFuncSetAttribute(mk_mma_kernel<2>,
                         cudaFuncAttributeMaxDynamicSharedMemorySize, SM_TOT);

    embed_kernel<<<Mm, 256>>>(inp, tok, pos);
    wsplit_kernel<<<dim3(Hh, Ee / 64, 3), 256>>>(Wk, Wq, Wv);

    // QKV: one GEMM, M=4096, N=3072
    mk_mma_kernel<2><<<dim3(Mm / 128, 3 * Ee / 256), 256, SM_TOT>>>(
        (const __nv_bfloat16*)pxh, (const __nv_bfloat16*)pxl,
        (const __nv_bfloat16*)pwh, (const __nv_bfloat16*)pwl,
        nullptr, (float*)pkqv, nullptr, nullptr);

    size_t smem = (size_t)(64 * 64 + 64 * KST + 64 * 64 + 64 * 64) * sizeof(float);
    cudaFuncSetAttribute(attn_kernel, cudaFuncAttributeMaxDynamicSharedMemorySize,
                         (int)smem);
    attn_kernel<<<dim3(Bb * Hh, Tt / 64), 256, smem>>>();

    cvt_transpose_kernel<<<dim3(Ee / 64, Ee / 64), 256>>>(
        ffW, (__nv_bfloat16*)pfh, (__nv_bfloat16*)pfl, Ee);
    mk_mma_kernel<1><<<dim3(Mm / 128, Ee / 256), 256, SM_TOT>>>(
        (const __nv_bfloat16*)pzh, (const __nv_bfloat16*)pzl,
        (const __nv_bfloat16*)pfh, (const __nv_bfloat16*)pfl,
        ffb, nullptr, (__nv_bfloat16*)pah, (__nv_bfloat16*)pal);

    cvt_transpose_kernel<<<dim3(Vv / 64, Ee / 64), 256>>>(
        oW, (__nv_bfloat16*)pbh, (__nv_bfloat16*)pbl, Vv);
    mk_mma_kernel<0><<<dim3(Mm / 128, Vv / 256), 256, SM_TOT>>>(
        (const __nv_bfloat16*)pah, (const __nv_bfloat16*)pal,
        (const __nv_bfloat16*)pbh, (const __nv_bfloat16*)pbl,
        ob, out, nullptr, nullptr);
}